// round 11
// baseline (speedup 1.0000x reference)
#include <cuda_runtime.h>
#include <cuda_fp16.h>
#include <cstdint>

#define ALPHA 0.9f
constexpr int T_LEN = 809;
constexpr int TPAD  = 810;
constexpr int DD    = 304;
constexpr int EE    = 300;
constexpr int LQ    = 30;
constexpr int BB    = 4;
constexpr int MSPAN = 16;
constexpr int H1    = 1024;
constexpr int H2    = 512;
constexpr int CIN   = 1212;
constexpr int NCAND = 12824;
constexpr int ROWS  = BB * NCAND;      // 51296
constexpr int MROWS = BB * TPAD;       // 3240
constexpr float EPS = 1e-5f;

// ---------------- scratch ----------------
__device__ __align__(16) __half g_Fph[MROWS * DD];
__device__ __align__(16) __half g_Fpl[MROWS * DD];
__device__ __align__(16) __half g_Rph[MROWS * DD];
__device__ __align__(16) __half g_Rpl[MROWS * DD];
__device__ __align__(16) __half g_W1h3[3 * DD * H1];
__device__ __align__(16) __half g_PX[MROWS * H1];   // fp16(PA + Pq)
__device__ __align__(16) __half g_PY[MROWS * H1];   // fp16(PB)
__device__ __align__(16) __half g_PE[MROWS * H1];   // fp16(PB + PC)
__device__ float g_Pq[BB * H1];
__device__ __align__(16) __half g_W2h16[H1 * H2];   // fp16(W2*sc2), [k][n]
__device__ float g_sh2[H2];
__device__ float g_coef[MSPAN];
__device__ int   g_sidx[NCAND];
__device__ int   g_eidx[NCAND];

// ---------------- helpers ----------------
__device__ __forceinline__ uint32_t smem_u32(const void* p) {
    uint32_t a;
    asm("{ .reg .u64 t; cvta.to.shared.u64 t, %1; cvt.u32.u64 %0, t; }" : "=r"(a) : "l"(p));
    return a;
}
__device__ __forceinline__ uint32_t h2u(__half2 h) { return *(uint32_t*)&h; }

__device__ __forceinline__ void ldsm_x4(uint32_t* r, uint32_t a) {
    asm volatile("ldmatrix.sync.aligned.m8n8.x4.shared.b16 {%0,%1,%2,%3}, [%4];"
                 : "=r"(r[0]), "=r"(r[1]), "=r"(r[2]), "=r"(r[3]) : "r"(a));
}
__device__ __forceinline__ void ldsm_x4_t(uint32_t* r, uint32_t a) {
    asm volatile("ldmatrix.sync.aligned.m8n8.x4.trans.shared.b16 {%0,%1,%2,%3}, [%4];"
                 : "=r"(r[0]), "=r"(r[1]), "=r"(r[2]), "=r"(r[3]) : "r"(a));
}
__device__ __forceinline__ void mma16816(float* d, const uint32_t* a, const uint32_t* b) {
    asm volatile(
        "mma.sync.aligned.m16n8k16.row.col.f32.f16.f16.f32 "
        "{%0,%1,%2,%3}, {%4,%5,%6,%7}, {%8,%9}, {%0,%1,%2,%3};"
        : "+f"(d[0]), "+f"(d[1]), "+f"(d[2]), "+f"(d[3])
        : "r"(a[0]), "r"(a[1]), "r"(a[2]), "r"(a[3]), "r"(b[0]), "r"(b[1]));
}
__device__ __forceinline__ void cp16(uint32_t dst, const void* src) {
    asm volatile("cp.async.cg.shared.global [%0], [%1], 16;" :: "r"(dst), "l"(src));
}
__device__ __forceinline__ void cp4(uint32_t dst, const void* src) {
    asm volatile("cp.async.ca.shared.global [%0], [%1], 4;" :: "r"(dst), "l"(src));
}
__device__ __forceinline__ void cp_commit() { asm volatile("cp.async.commit_group;"); }
template <int N> __device__ __forceinline__ void cp_wait() {
    asm volatile("cp.async.wait_group %0;" :: "n"(N));
}

// =================== fat prep kernel ==============
constexpr int PREP_W2   = 512;
constexpr int PREP_W1   = 960;
constexpr int PREP_SCAN = 8;
constexpr int PREP_PQ   = 512;
constexpr int PREP_MISC = 64;
constexpr int PREP_GRID = PREP_W2 + PREP_W1 + PREP_SCAN + PREP_PQ + PREP_MISC;

__global__ void __launch_bounds__(256) k_prep(
    const float* __restrict__ doc, const float* __restrict__ Qe,
    const float* __restrict__ W1,
    const float* __restrict__ g1, const float* __restrict__ b1,
    const float* __restrict__ m1, const float* __restrict__ v1,
    const float* __restrict__ W2,
    const float* __restrict__ g2, const float* __restrict__ b2,
    const float* __restrict__ m2, const float* __restrict__ v2,
    float* __restrict__ out) {
    __shared__ float sh[32 * DD];
    int bx = blockIdx.x;
    const int tid = threadIdx.x;

    if (bx < PREP_W2) {
        float (*tl)[33] = (float(*)[33])sh;
        const int kt = bx & 31, nt = bx >> 5;
        const int k0 = kt * 32, n0 = nt * 32;
        const int tx = tid & 31, ty = tid >> 5;
#pragma unroll
        for (int it = 0; it < 4; it++)
            tl[ty + it * 8][tx] = W2[(size_t)(n0 + ty + it * 8) * H1 + k0 + tx];
        __syncthreads();
        const int n = n0 + tx;
        const float sc = g2[n] * rsqrtf(v2[n] + EPS);
#pragma unroll
        for (int it = 0; it < 4; it++) {
            int k = k0 + ty + it * 8;
            g_W2h16[(size_t)k * H2 + n] = __float2half_rn(tl[tx][ty + it * 8] * sc);
        }
        return;
    }
    bx -= PREP_W2;
    if (bx < PREP_W1) {
        float (*tl)[33] = (float(*)[33])sh;
        const int z = bx / 320;
        const int r = bx - z * 320;
        const int kt = r % 10, nt = r / 10;
        const int k0 = kt * 32, n0 = nt * 32;
        const int tx = tid & 31, ty = tid >> 5;
#pragma unroll
        for (int it = 0; it < 4; it++) {
            int n = n0 + ty + it * 8;
            int k = k0 + tx;
            tl[ty + it * 8][tx] = (k < DD) ? W1[(size_t)n * CIN + z * DD + k] : 0.f;
        }
        __syncthreads();
        const int n = n0 + tx;
        const float sc = g1[n] * rsqrtf(v1[n] + EPS);
#pragma unroll
        for (int it = 0; it < 4; it++) {
            int k = k0 + ty + it * 8;
            if (k >= DD) continue;
            g_W1h3[((size_t)(z * DD + k)) * H1 + n] =
                __float2half_rn(tl[tx][ty + it * 8] * sc);
        }
        return;
    }
    bx -= PREP_W1;
    if (bx < PREP_SCAN) {
        const int b = bx >> 1;
        const float* dp = doc + (size_t)b * T_LEN * DD;
        const int d0 = tid, d1 = tid + 256;
        const bool has1 = (d1 < DD);
        if ((bx & 1) == 0) {
            float a0 = 0.f, a1 = 0.f;
            __half* fh = g_Fph + (size_t)(b * TPAD) * DD;
            __half* fl = g_Fpl + (size_t)(b * TPAD) * DD;
            for (int d = tid; d < DD; d += 256) {
                fh[d] = __float2half_rn(0.f);
                fl[d] = __float2half_rn(0.f);
            }
            for (int t0 = 0; t0 < T_LEN; t0 += 32) {
                int n = min(32, T_LEN - t0);
                __syncthreads();
                for (int i = tid; i < n * DD; i += 256) sh[i] = dp[(size_t)t0 * DD + i];
                __syncthreads();
                for (int i = 0; i < n; i++) {
                    size_t ro = (size_t)(t0 + i + 1) * DD;
                    a0 = fmaf(ALPHA, a0, sh[i * DD + d0]);
                    __half h0 = __float2half_rn(a0);
                    fh[ro + d0] = h0;
                    fl[ro + d0] = __float2half_rn(a0 - __half2float(h0));
                    if (has1) {
                        a1 = fmaf(ALPHA, a1, sh[i * DD + d1]);
                        __half h1v = __float2half_rn(a1);
                        fh[ro + d1] = h1v;
                        fl[ro + d1] = __float2half_rn(a1 - __half2float(h1v));
                    }
                }
            }
        } else {
            float a0 = 0.f, a1 = 0.f;
            __half* rh = g_Rph + (size_t)(b * TPAD) * DD;
            __half* rl = g_Rpl + (size_t)(b * TPAD) * DD;
            for (int d = tid; d < DD; d += 256) {
                rh[(size_t)T_LEN * DD + d] = __float2half_rn(0.f);
                rl[(size_t)T_LEN * DD + d] = __float2half_rn(0.f);
            }
            for (int hi = T_LEN; hi > 0; hi -= 32) {
                int lo = (hi > 32) ? hi - 32 : 0;
                int n = hi - lo;
                __syncthreads();
                for (int i = tid; i < n * DD; i += 256) sh[i] = dp[(size_t)lo * DD + i];
                __syncthreads();
                for (int i = n - 1; i >= 0; i--) {
                    size_t ro = (size_t)(lo + i) * DD;
                    a0 = fmaf(ALPHA, a0, sh[i * DD + d0]);
                    __half h0 = __float2half_rn(a0);
                    rh[ro + d0] = h0;
                    rl[ro + d0] = __float2half_rn(a0 - __half2float(h0));
                    if (has1) {
                        a1 = fmaf(ALPHA, a1, sh[i * DD + d1]);
                        __half h1v = __float2half_rn(a1);
                        rh[ro + d1] = h1v;
                        rl[ro + d1] = __float2half_rn(a1 - __half2float(h1v));
                    }
                }
            }
        }
        return;
    }
    bx -= PREP_SCAN;
    if (bx < PREP_PQ) {
        const int lane = tid & 31;
        const int gw = bx * 8 + (tid >> 5);
        const int j = gw & (H1 - 1);
        const int b = gw >> 10;
        const float sc = g1[j] * rsqrtf(v1[j] + EPS);
        const float* wrow = &W1[(size_t)j * CIN + 3 * DD];
        float dot = 0.f;
        for (int d = lane; d < EE; d += 32) {
            float qv = 0.f, p = 1.f;
#pragma unroll
            for (int t = LQ - 1; t >= 0; t--) {
                qv = fmaf(p, Qe[(b * LQ + t) * EE + d], qv);
                p *= ALPHA;
            }
            dot = fmaf(qv, wrow[d], dot);
        }
#pragma unroll
        for (int o = 16; o > 0; o >>= 1) dot += __shfl_xor_sync(0xffffffffu, dot, o);
        if (lane == 0) g_Pq[b * H1 + j] = b1[j] - m1[j] * sc + sc * dot;
        return;
    }
    bx -= PREP_PQ;
    {
        const long total = H2 + T_LEN + MSPAN + (long)ROWS * 2;
        for (long idx = (long)bx * 256 + tid; idx < total; idx += (long)PREP_MISC * 256) {
            long i = idx;
            if (i < H2) {
                float sc = g2[i] * rsqrtf(v2[i] + EPS);
                g_sh2[i] = b2[i] - m2[i] * sc;
                continue;
            }
            i -= H2;
            if (i < T_LEN) {
                int s = (int)i;
                int cnt = min(MSPAN, T_LEN - s);
                int ex = (s > 794) ? ((s - 794) * (s - 793)) / 2 : 0;
                int base = 16 * s - ex;
                for (int sp = 0; sp < cnt; sp++) {
                    g_sidx[base + sp] = s;
                    g_eidx[base + sp] = s + sp;
                }
                continue;
            }
            i -= T_LEN;
            if (i < MSPAN) {
                double c = 1.0;
                for (int k = 0; k <= (int)i; k++) c *= 0.9;
                g_coef[i] = (float)c;
                continue;
            }
            i -= MSPAN;
            out[i] = 0.f;   // zero output for atomicAdd accumulation
        }
    }
}

// ---------- projections: fp16 mma, single launch; z2 = Fp@W1b + Rp@W1c -> PE ----
constexpr int PJ_SA = 48;
constexpr int PJ_SB = 272;
constexpr uint32_t PJ_AHF = 0;
constexpr uint32_t PJ_ALF = 6144;
constexpr uint32_t PJ_AHR = 12288;
constexpr uint32_t PJ_ALR = 18432;
constexpr uint32_t PJ_BB  = 24576;
constexpr uint32_t PJ_BC  = 28928;
constexpr uint32_t PJ_STAGE = 33280;
constexpr uint32_t PJ_SMEM = 2 * PJ_STAGE;   // 66560

__global__ void __launch_bounds__(256) k_proj() {
    extern __shared__ char sm[];
    const uint32_t sb = smem_u32(sm);
    const int z = blockIdx.z;
    const int m0 = blockIdx.x * 128;
    const int n0 = blockIdx.y * 128;
    const int tid = threadIdx.x;
    const int lane = tid & 31;
    const int w = tid >> 5;
    const int mw = w & 3;
    const int nw = w >> 2;

    __half* P = (z == 0) ? g_PX : (z == 1 ? g_PY : g_PE);

    const int amm = tid >> 1, aseg = tid & 1;
    const int am = (m0 + amm < MROWS) ? (m0 + amm) : 0;
    const int bkr = tid >> 4, bns = tid & 15;

    auto stage = [&](int cc) {
        const uint32_t st = sb + (uint32_t)(cc & 1) * PJ_STAGE;
        const int k0 = cc * 16;
        const size_t asrc = ((size_t)am * DD + k0 + aseg * 8);
        const uint32_t adst = (uint32_t)(amm * PJ_SA + aseg * 16);
        if (z < 2) {
            cp16(st + PJ_AHF + adst, g_Fph + asrc);
            cp16(st + PJ_ALF + adst, g_Fpl + asrc);
            const size_t bsrc = ((size_t)(z * DD + k0 + bkr)) * H1 + n0 + bns * 8;
            cp16(st + PJ_BB + (uint32_t)(bkr * PJ_SB + bns * 16), g_W1h3 + bsrc);
        } else {
            cp16(st + PJ_AHF + adst, g_Fph + asrc);
            cp16(st + PJ_ALF + adst, g_Fpl + asrc);
            cp16(st + PJ_AHR + adst, g_Rph + asrc);
            cp16(st + PJ_ALR + adst, g_Rpl + asrc);
            const size_t bsb = ((size_t)(1 * DD + k0 + bkr)) * H1 + n0 + bns * 8;
            const size_t bsc = ((size_t)(2 * DD + k0 + bkr)) * H1 + n0 + bns * 8;
            cp16(st + PJ_BB + (uint32_t)(bkr * PJ_SB + bns * 16), g_W1h3 + bsb);
            cp16(st + PJ_BC + (uint32_t)(bkr * PJ_SB + bns * 16), g_W1h3 + bsc);
        }
        cp_commit();
    };

    float acc[2][8][4];
#pragma unroll
    for (int i = 0; i < 2; i++)
#pragma unroll
        for (int j = 0; j < 8; j++)
#pragma unroll
            for (int c = 0; c < 4; c++) acc[i][j][c] = 0.f;

    const uint32_t aRel = (uint32_t)((mw * 32 + (lane & 15)) * PJ_SA + (lane >> 4) * 16);
    const uint32_t bRel = (uint32_t)((lane & 15) * PJ_SB + (nw * 64 + (lane >> 4) * 8) * 2);

    stage(0);
#pragma unroll 1
    for (int c = 0; c < 19; c++) {
        if (c < 18) { stage(c + 1); cp_wait<1>(); }
        else        { cp_wait<0>(); }
        __syncthreads();
        const uint32_t st = sb + (uint32_t)(c & 1) * PJ_STAGE;
        uint32_t ah[2][4], al[2][4];
        ldsm_x4(ah[0], st + PJ_AHF + aRel);
        ldsm_x4(ah[1], st + PJ_AHF + aRel + 16 * PJ_SA);
        ldsm_x4(al[0], st + PJ_ALF + aRel);
        ldsm_x4(al[1], st + PJ_ALF + aRel + 16 * PJ_SA);
#pragma unroll
        for (int g = 0; g < 4; g++) {
            uint32_t bh[4];
            ldsm_x4_t(bh, st + PJ_BB + bRel + g * 32);
#pragma unroll
            for (int m = 0; m < 2; m++) {
                mma16816(acc[m][2 * g],     ah[m], bh);
                mma16816(acc[m][2 * g + 1], ah[m], bh + 2);
                mma16816(acc[m][2 * g],     al[m], bh);
                mma16816(acc[m][2 * g + 1], al[m], bh + 2);
            }
        }
        if (z == 2) {
            uint32_t ahr[2][4], alr[2][4];
            ldsm_x4(ahr[0], st + PJ_AHR + aRel);
            ldsm_x4(ahr[1], st + PJ_AHR + aRel + 16 * PJ_SA);
            ldsm_x4(alr[0], st + PJ_ALR + aRel);
            ldsm_x4(alr[1], st + PJ_ALR + aRel + 16 * PJ_SA);
#pragma unroll
            for (int g = 0; g < 4; g++) {
                uint32_t bh[4];
                ldsm_x4_t(bh, st + PJ_BC + bRel + g * 32);
#pragma unroll
                for (int m = 0; m < 2; m++) {
                    mma16816(acc[m][2 * g],     ahr[m], bh);
                    mma16816(acc[m][2 * g + 1], ahr[m], bh + 2);
                    mma16816(acc[m][2 * g],     alr[m], bh);
                    mma16816(acc[m][2 * g + 1], alr[m], bh + 2);
                }
            }
        }
        __syncthreads();
    }

#pragma unroll
    for (int m = 0; m < 2; m++) {
        int row0 = m0 + mw * 32 + m * 16 + (lane >> 2);
#pragma unroll
        for (int h = 0; h < 2; h++) {
            int row = row0 + h * 8;
            if (row >= MROWS) continue;
            const int col = n0 + nw * 64 + (lane & 3) * 2;
            __half2* pr = (__half2*)&P[(size_t)row * H1 + col];
            const float* qr = (z == 0) ? &g_Pq[(row / TPAD) * H1 + col] : nullptr;
#pragma unroll
            for (int nf = 0; nf < 8; nf++) {
                float vx = acc[m][nf][2 * h];
                float vy = acc[m][nf][2 * h + 1];
                if (z == 0) {
                    vx += qr[nf * 8];
                    vy += qr[nf * 8 + 1];
                }
                pr[nf * 4] = __floats2half2_rn(vx, vy);
            }
        }
    }
}

// ---- main: fp16 mma GEMM2, M=64/N=256, 2 CTAs/SM, cp.async-gathered A-gen ----
constexpr int SA_STRIDE = 144;
constexpr int SB_STRIDE = 528;
constexpr uint32_t OFF_AH   = 0;                // 64*144  = 9216
constexpr uint32_t OFF_BH   = 9216;             // 64*528  = 33792
constexpr uint32_t OFF_E    = 43008;            // 64*128  = 8192 (E raw staging)
constexpr uint32_t STAGE_SZ = 51200;
constexpr uint32_t OFF_HDR  = 102400;
constexpr uint32_t OFF_OS   = OFF_HDR;
constexpr uint32_t OFF_OE   = OFF_HDR + 256;
constexpr uint32_t OFF_CF   = OFF_HDR + 512;
constexpr uint32_t OFF_W3A  = OFF_HDR + 768;
constexpr uint32_t OFF_W3B  = OFF_HDR + 1792;
constexpr uint32_t OFF_SH2  = OFF_HDR + 2816;
constexpr uint32_t OFF_RED  = OFF_HDR + 3840;
constexpr uint32_t SMEM_MAIN = OFF_HDR + 5888;  // 108288 (x2 CTAs/SM = 216576)

__global__ void __launch_bounds__(256, 2) k_main(const float* __restrict__ W3,
                                                 float* __restrict__ out) {
    extern __shared__ char sm[];
    const uint32_t sb = smem_u32(sm);
    const int tid = threadIdx.x;
    const int lane = tid & 31;
    const int w = tid >> 5;
    const int mw = w & 1;
    const int nw = w >> 1;
    const int batch = blockIdx.y;
    const int c0i = blockIdx.x * 64;
    const int n0 = blockIdx.z * 256;

    int*   sOS = (int*)(sm + OFF_OS);
    int*   sOE = (int*)(sm + OFF_OE);
    float* sCF = (float*)(sm + OFF_CF);
    float* sW3a = (float*)(sm + OFF_W3A);
    float* sW3b = (float*)(sm + OFF_W3B);
    float* sSh2 = (float*)(sm + OFF_SH2);
    float* sRed = (float*)(sm + OFF_RED);

    if (tid < 64) {
        int ci = c0i + tid;
        int offS = 0, offE = 0;
        float cf = 0.f;
        if (ci < NCAND) {
            int s = g_sidx[ci], e = g_eidx[ci];
            offS = (batch * TPAD + s) * H1;
            offE = (batch * TPAD + e + 1) * H1;
            cf = g_coef[e - s];
        }
        sOS[tid] = offS; sOE[tid] = offE; sCF[tid] = cf;
    }
    sW3a[tid] = W3[n0 + tid];
    sW3b[tid] = W3[H2 + n0 + tid];
    sSh2[tid] = g_sh2[n0 + tid];
    __syncthreads();

    const int wrow = w * 8;
    const int myOS = sOS[wrow + (lane & 7)];
    const int myOE = sOE[wrow + (lane & 7)];
    const float myCF = sCF[wrow + (lane & 7)];
    const bool uni = (__shfl_sync(0xffffffffu, myOS, 0) ==
                      __shfl_sync(0xffffffffu, myOS, 7));
    const int offSu = __shfl_sync(0xffffffffu, myOS, 0);

    const int bkr = tid >> 5;
    const int bnc = tid & 31;

    const uint32_t aRel = OFF_AH + (uint32_t)((mw * 32 + (lane & 15)) * SA_STRIDE +
                                              ((lane >> 4) * 8) * 2);
    const uint32_t bRel = OFF_BH + (uint32_t)((lane & 15) * SB_STRIDE +
                                              (nw * 64 + (lane >> 4) * 8) * 2);

    float acc[2][8][4];
#pragma unroll
    for (int t = 0; t < 2; t++)
#pragma unroll
        for (int nf = 0; nf < 8; nf++)
#pragma unroll
            for (int c = 0; c < 4; c++) acc[t][nf][c] = 0.f;

    // issue B (cp16) + E gathers (cp4, per-thread-own) for chunk cc; one commit group
    auto issueBE = [&](int cc) {
        const uint32_t st = sb + (uint32_t)(cc & 1) * STAGE_SZ;
        const __half* bsrc = &g_W2h16[(size_t)(cc * 64) * H2 + n0];
#pragma unroll
        for (int it = 0; it < 8; it++) {
            int kr = bkr + it * 8;
            cp16(st + OFF_BH + (uint32_t)(kr * SB_STRIDE + bnc * 16),
                 bsrc + (size_t)kr * H2 + bnc * 8);
        }
        const int kc = cc * 64 + 2 * lane;
#pragma unroll
        for (int rr = 0; rr < 8; rr++) {
            int offE = __shfl_sync(0xffffffffu, myOE, rr);
            cp4(st + OFF_E + (uint32_t)((wrow + rr) * 128 + lane * 4),
                &g_PE[offE + kc]);
        }
        cp_commit();
    };

    float2 xv, yv;   // uni-path prefetch registers
    auto prefXY = [&](int cc) {
        if (uni) {
            const int kc = cc * 64 + 2 * lane;
            xv = __half22float2(*(const __half2*)&g_PX[offSu + kc]);
            yv = __half22float2(*(const __half2*)&g_PY[offSu + kc]);
        }
    };

    // convert E staging + x/y into fp16 A operand tile (own-thread E only)
    auto cvtSTS = [&](int cc) {
        const uint32_t stoff = (uint32_t)(cc & 1) * STAGE_SZ;
        const int kc = cc * 64 + 2 * lane;
        if (uni) {
#pragma unroll
            for (int rr = 0; rr < 8; rr++) {
                float cf = __shfl_sync(0xffffffffu, myCF, rr);
                __half2 eh = *(__half2*)(sm + stoff + OFF_E + (wrow + rr) * 128 + lane * 4);
                float2 e = __half22float2(eh);
                float v0 = fmaxf(xv.x + e.x - cf * yv.x, 0.f);
                float v1 = fmaxf(xv.y + e.y - cf * yv.y, 0.f);
                __half2 h = __floats2half2_rn(v0, v1);
                uint32_t ad = stoff + (uint32_t)((wrow + rr) * SA_STRIDE + lane * 4);
                *(uint32_t*)(sm + OFF_AH + ad) = h2u(h);
            }
        } else {
#pragma unroll
            for (int rr = 0; rr < 8; rr++) {
                int offS = __shfl_sync(0xffffffffu, myOS, rr);
                float cf = __shfl_sync(0xffffffffu, myCF, rr);
                float2 x = __half22float2(*(const __half2*)&g_PX[offS + kc]);
                float2 y = __half22float2(*(const __half2*)&g_PY[offS + kc]);
                __half2 eh = *(__half2*)(sm + stoff + OFF_E + (wrow + rr) * 128 + lane * 4);
                float2 e = __half22float2(eh);
                float v0 = fmaxf(x.x + e.x - cf * y.x, 0.f);
                float v1 = fmaxf(x.y + e.y - cf * y.y, 0.f);
                __half2 h = __floats2half2_rn(v0, v1);
                uint32_t ad = stoff + (uint32_t)((wrow + rr) * SA_STRIDE + lane * 4);
                *(uint32_t*)(sm + OFF_AH + ad) = h2u(h);
            }
        }
    };

    issueBE(0);
    prefXY(0);

#pragma unroll 1
    for (int c = 0; c < 16; c++) {
        cp_wait<0>();          // own E(c) + own B(c) copies done
        cvtSTS(c);             // A(c) -> buf c&1 (prior reader mma(c-2): sync(c-1) separates)
        __syncthreads();       // publish all B(c) + A(c)
        if (c < 15) {          // buf (c+1)&1 writes vs mma(c-1): sync(c) separates
            issueBE(c + 1);    // latency hides under mma(c)
            prefXY(c + 1);
        }
        const uint32_t st = sb + (uint32_t)(c & 1) * STAGE_SZ;
#pragma unroll
        for (int s = 0; s < 4; s++) {
            const uint32_t ka = st + aRel + (uint32_t)(s * 32);
            uint32_t ah[2][4];
            ldsm_x4(ah[0], ka);
            ldsm_x4(ah[1], ka + 16 * SA_STRIDE);
            const uint32_t kbq = st + bRel + (uint32_t)(s * 16 * SB_STRIDE);
#pragma unroll
            for (int p = 0; p < 4; p++) {
                uint32_t bq[4];
                ldsm_x4_t(bq, kbq + p * 32);
                mma16816(acc[0][2 * p],     ah[0], bq);
                mma16816(acc[1][2 * p],     ah[1], bq);
                mma16816(acc[0][2 * p + 1], ah[0], bq + 2);
                mma16816(acc[1][2 * p + 1], ah[1], bq + 2);
            }
        }
    }

    // ---- epilogue: relu(D + sh2) dot W3, reduce lanes + 4 N-groups, atomicAdd ----
    float sums[4][2];
#pragma unroll
    for (int q = 0; q < 4; q++) { sums[q][0] = 0.f; sums[q][1] = 0.f; }
#pragma unroll
    for (int t = 0; t < 2; t++) {
#pragma unroll
        for (int nf = 0; nf < 8; nf++) {
            int n = nw * 64 + nf * 8 + (lane & 3) * 2;
            float sh0 = sSh2[n], sh1 = sSh2[n + 1];
            float wa0 = sW3a[n], wa1 = sW3a[n + 1];
            float wb0 = sW3b[n], wb1 = sW3b[n + 1];
            float v0 = fmaxf(acc[t][nf][0] + sh0, 0.f);
            float v1 = fmaxf(acc[t][nf][1] + sh1, 0.f);
            float v2 = fmaxf(acc[t][nf][2] + sh0, 0.f);
            float v3 = fmaxf(acc[t][nf][3] + sh1, 0.f);
            sums[t * 2][0]     = fmaf(v0, wa0, fmaf(v1, wa1, sums[t * 2][0]));
            sums[t * 2][1]     = fmaf(v0, wb0, fmaf(v1, wb1, sums[t * 2][1]));
            sums[t * 2 + 1][0] = fmaf(v2, wa0, fmaf(v3, wa1, sums[t * 2 + 1][0]));
            sums[t * 2 + 1][1] = fmaf(v2, wb0, fmaf(v3, wb1, sums[t * 2 + 1][1]));
        }
    }
#pragma unroll
    for (int q = 0; q < 4; q++) {
#pragma unroll
        for (int o = 0; o < 2; o++) {
            sums[q][o] += __shfl_xor_sync(0xffffffffu, sums[q][o], 1);
            sums[q][o] += __shfl_xor_sync(0xffffffffu, sums[q][o], 2);
        }
    }
    __syncthreads();
    if ((lane & 3) == 0) {
#pragma unroll
        for (int q = 0; q < 4; q++) {
            int rloc = mw * 32 + (q >> 1) * 16 + (q & 1) * 8 + (lane >> 2);
            sRed[nw * 128 + rloc * 2 + 0] = sums[q][0];
            sRed[nw * 128 + rloc * 2 + 1] = sums[q][1];
        }
    }
    __syncthreads();
    if (tid < 128) {
        int rloc = tid >> 1, o = tid & 1;
        int ci = c0i + rloc;
        if (ci < NCAND) {
            float v = sRed[rloc * 2 + o] + sRed[128 + rloc * 2 + o] +
                      sRed[256 + rloc * 2 + o] + sRed[384 + rloc * 2 + o];
            atomicAdd(&out[(size_t)(batch * NCAND + ci) * 2 + o], v);
        }
    }
}

// ---------------- launch ----------------
extern "C" void kernel_launch(void* const* d_in, const int* in_sizes, int n_in,
                              void* d_out, int out_size) {
    (void)in_sizes; (void)n_in; (void)out_size;
    const float* doc = (const float*)d_in[0];
    const float* qe  = (const float*)d_in[1];
    const float* W1  = (const float*)d_in[2];
    const float* g1  = (const float*)d_in[3];
    const float* b1  = (const float*)d_in[4];
    const float* m1  = (const float*)d_in[5];
    const float* v1  = (const float*)d_in[6];
    const float* W2  = (const float*)d_in[7];
    const float* g2  = (const float*)d_in[8];
    const float* b2  = (const float*)d_in[9];
    const float* m2  = (const float*)d_in[10];
    const float* v2  = (const float*)d_in[11];
    const float* W3  = (const float*)d_in[12];
    float* out = (float*)d_out;

    cudaFuncSetAttribute(k_main, cudaFuncAttributeMaxDynamicSharedMemorySize, SMEM_MAIN);
    cudaFuncSetAttribute(k_proj, cudaFuncAttributeMaxDynamicSharedMemorySize, PJ_SMEM);

    k_prep<<<PREP_GRID, 256>>>(doc, qe, W1, g1, b1, m1, v1, W2, g2, b2, m2, v2, out);
    k_proj<<<dim3((MROWS + 127) / 128, H1 / 128, 3), 256, PJ_SMEM>>>();
    k_main<<<dim3((NCAND + 63) / 64, BB, 2), 256, SMEM_MAIN>>>(W3, out);
}

// round 12
// speedup vs baseline: 1.2629x; 1.2629x over previous
#include <cuda_runtime.h>
#include <cuda_fp16.h>
#include <cstdint>

#define ALPHA 0.9f
constexpr int T_LEN = 809;
constexpr int TPAD  = 810;
constexpr int DD    = 304;
constexpr int EE    = 300;
constexpr int LQ    = 30;
constexpr int BB    = 4;
constexpr int MSPAN = 16;
constexpr int H1    = 1024;
constexpr int H2    = 512;
constexpr int CIN   = 1212;
constexpr int NCAND = 12824;
constexpr int ROWS  = BB * NCAND;      // 51296
constexpr int MROWS = BB * TPAD;       // 3240
constexpr float EPS = 1e-5f;
constexpr int CLEN   = 64;             // scan chunk length
constexpr int NCHUNK = 13;             // ceil(809/64)

// ---------------- scratch ----------------
__device__ __align__(16) __half g_Fph[MROWS * DD];
__device__ __align__(16) __half g_Fpl[MROWS * DD];
__device__ __align__(16) __half g_Rph[MROWS * DD];
__device__ __align__(16) __half g_Rpl[MROWS * DD];
__device__ __align__(16) float g_Ltmp[MROWS * DD];   // forward local scans (row t+1)
__device__ __align__(16) float g_Mtmp[MROWS * DD];   // reverse local scans (row t)
__device__ float g_carryF[BB * NCHUNK * DD];
__device__ float g_carryR[BB * NCHUNK * DD];
__device__ float g_apow[CLEN + 1];
__device__ __align__(16) __half g_W1h3[3 * DD * H1];
__device__ __align__(16) __half g_PX[MROWS * H1];   // fp16(PA + Pq)
__device__ __align__(16) __half g_PY[MROWS * H1];   // fp16(PB)
__device__ __align__(16) __half g_PE[MROWS * H1];   // fp16(PB + PC)
__device__ float g_Pq[BB * H1];
__device__ __align__(16) __half g_W2h16[H1 * H2];   // fp16(W2*sc2), [k][n]
__device__ float g_sh2[H2];
__device__ float g_coef[MSPAN];
__device__ int   g_sidx[NCAND];
__device__ int   g_eidx[NCAND];

// ---------------- helpers ----------------
__device__ __forceinline__ uint32_t smem_u32(const void* p) {
    uint32_t a;
    asm("{ .reg .u64 t; cvta.to.shared.u64 t, %1; cvt.u32.u64 %0, t; }" : "=r"(a) : "l"(p));
    return a;
}
__device__ __forceinline__ uint32_t h2u(__half2 h) { return *(uint32_t*)&h; }

__device__ __forceinline__ void ldsm_x4(uint32_t* r, uint32_t a) {
    asm volatile("ldmatrix.sync.aligned.m8n8.x4.shared.b16 {%0,%1,%2,%3}, [%4];"
                 : "=r"(r[0]), "=r"(r[1]), "=r"(r[2]), "=r"(r[3]) : "r"(a));
}
__device__ __forceinline__ void ldsm_x4_t(uint32_t* r, uint32_t a) {
    asm volatile("ldmatrix.sync.aligned.m8n8.x4.trans.shared.b16 {%0,%1,%2,%3}, [%4];"
                 : "=r"(r[0]), "=r"(r[1]), "=r"(r[2]), "=r"(r[3]) : "r"(a));
}
__device__ __forceinline__ void mma16816(float* d, const uint32_t* a, const uint32_t* b) {
    asm volatile(
        "mma.sync.aligned.m16n8k16.row.col.f32.f16.f16.f32 "
        "{%0,%1,%2,%3}, {%4,%5,%6,%7}, {%8,%9}, {%0,%1,%2,%3};"
        : "+f"(d[0]), "+f"(d[1]), "+f"(d[2]), "+f"(d[3])
        : "r"(a[0]), "r"(a[1]), "r"(a[2]), "r"(a[3]), "r"(b[0]), "r"(b[1]));
}
__device__ __forceinline__ void cp16(uint32_t dst, const void* src) {
    asm volatile("cp.async.cg.shared.global [%0], [%1], 16;" :: "r"(dst), "l"(src));
}
__device__ __forceinline__ void cp_commit() { asm volatile("cp.async.commit_group;"); }
template <int N> __device__ __forceinline__ void cp_wait() {
    asm volatile("cp.async.wait_group %0;" :: "n"(N));
}

// =================== fat prep kernel ==============
constexpr int PREP_W2   = 512;
constexpr int PREP_W1   = 960;
constexpr int PREP_SC1  = BB * 2 * NCHUNK;   // 104 local-scan blocks
constexpr int PREP_PQ   = 512;
constexpr int PREP_MISC = 64;
constexpr int PREP_GRID = PREP_W2 + PREP_W1 + PREP_SC1 + PREP_PQ + PREP_MISC;

__global__ void __launch_bounds__(256) k_prep(
    const float* __restrict__ doc, const float* __restrict__ Qe,
    const float* __restrict__ W1,
    const float* __restrict__ g1, const float* __restrict__ b1,
    const float* __restrict__ m1, const float* __restrict__ v1,
    const float* __restrict__ W2,
    const float* __restrict__ g2, const float* __restrict__ b2,
    const float* __restrict__ m2, const float* __restrict__ v2,
    float* __restrict__ out) {
    __shared__ float sh[32 * DD];
    int bx = blockIdx.x;
    const int tid = threadIdx.x;

    if (bx < PREP_W2) {
        float (*tl)[33] = (float(*)[33])sh;
        const int kt = bx & 31, nt = bx >> 5;
        const int k0 = kt * 32, n0 = nt * 32;
        const int tx = tid & 31, ty = tid >> 5;
#pragma unroll
        for (int it = 0; it < 4; it++)
            tl[ty + it * 8][tx] = W2[(size_t)(n0 + ty + it * 8) * H1 + k0 + tx];
        __syncthreads();
        const int n = n0 + tx;
        const float sc = g2[n] * rsqrtf(v2[n] + EPS);
#pragma unroll
        for (int it = 0; it < 4; it++) {
            int k = k0 + ty + it * 8;
            g_W2h16[(size_t)k * H2 + n] = __float2half_rn(tl[tx][ty + it * 8] * sc);
        }
        return;
    }
    bx -= PREP_W2;
    if (bx < PREP_W1) {
        float (*tl)[33] = (float(*)[33])sh;
        const int z = bx / 320;
        const int r = bx - z * 320;
        const int kt = r % 10, nt = r / 10;
        const int k0 = kt * 32, n0 = nt * 32;
        const int tx = tid & 31, ty = tid >> 5;
#pragma unroll
        for (int it = 0; it < 4; it++) {
            int n = n0 + ty + it * 8;
            int k = k0 + tx;
            tl[ty + it * 8][tx] = (k < DD) ? W1[(size_t)n * CIN + z * DD + k] : 0.f;
        }
        __syncthreads();
        const int n = n0 + tx;
        const float sc = g1[n] * rsqrtf(v1[n] + EPS);
#pragma unroll
        for (int it = 0; it < 4; it++) {
            int k = k0 + ty + it * 8;
            if (k >= DD) continue;
            g_W1h3[((size_t)(z * DD + k)) * H1 + n] =
                __float2half_rn(tl[tx][ty + it * 8] * sc);
        }
        return;
    }
    bx -= PREP_W1;
    if (bx < PREP_SC1) {
        // local scans: dir = bx&1, b = (bx>>1)/NCHUNK, chunk = (bx>>1)%NCHUNK
        const int dir = bx & 1;
        const int rest = bx >> 1;
        const int b = rest / NCHUNK;
        const int chunk = rest - b * NCHUNK;
        const int tstart = chunk * CLEN;
        const int tend = min(T_LEN, tstart + CLEN);
        const float* dp = doc + (size_t)b * T_LEN * DD;
        const int d0 = tid, d1 = tid + 256;
        const bool has1 = (d1 < DD);
        const size_t base = (size_t)b * TPAD * DD;
        if (dir == 0) {
            float a0 = 0.f, a1 = 0.f;
            for (int t0 = tstart; t0 < tend; t0 += 32) {
                int n = min(32, tend - t0);
                __syncthreads();
                for (int i = tid; i < n * DD; i += 256) sh[i] = dp[(size_t)t0 * DD + i];
                __syncthreads();
                for (int i = 0; i < n; i++) {
                    size_t ro = base + (size_t)(t0 + i + 1) * DD;
                    a0 = fmaf(ALPHA, a0, sh[i * DD + d0]);
                    g_Ltmp[ro + d0] = a0;
                    if (has1) {
                        a1 = fmaf(ALPHA, a1, sh[i * DD + d1]);
                        g_Ltmp[ro + d1] = a1;
                    }
                }
            }
        } else {
            float a0 = 0.f, a1 = 0.f;
            for (int hi = tend; hi > tstart; hi -= 32) {
                int lo = max(tstart, hi - 32);
                int n = hi - lo;
                __syncthreads();
                for (int i = tid; i < n * DD; i += 256) sh[i] = dp[(size_t)lo * DD + i];
                __syncthreads();
                for (int i = n - 1; i >= 0; i--) {
                    size_t ro = base + (size_t)(lo + i) * DD;
                    a0 = fmaf(ALPHA, a0, sh[i * DD + d0]);
                    g_Mtmp[ro + d0] = a0;
                    if (has1) {
                        a1 = fmaf(ALPHA, a1, sh[i * DD + d1]);
                        g_Mtmp[ro + d1] = a1;
                    }
                }
            }
        }
        return;
    }
    bx -= PREP_SC1;
    if (bx < PREP_PQ) {
        const int lane = tid & 31;
        const int gw = bx * 8 + (tid >> 5);
        const int j = gw & (H1 - 1);
        const int b = gw >> 10;
        const float sc = g1[j] * rsqrtf(v1[j] + EPS);
        const float* wrow = &W1[(size_t)j * CIN + 3 * DD];
        float dot = 0.f;
        for (int d = lane; d < EE; d += 32) {
            float qv = 0.f, p = 1.f;
#pragma unroll
            for (int t = LQ - 1; t >= 0; t--) {
                qv = fmaf(p, Qe[(b * LQ + t) * EE + d], qv);
                p *= ALPHA;
            }
            dot = fmaf(qv, wrow[d], dot);
        }
#pragma unroll
        for (int o = 16; o > 0; o >>= 1) dot += __shfl_xor_sync(0xffffffffu, dot, o);
        if (lane == 0) g_Pq[b * H1 + j] = b1[j] - m1[j] * sc + sc * dot;
        return;
    }
    bx -= PREP_PQ;
    {
        const long total = H2 + T_LEN + MSPAN + (CLEN + 1) + (long)ROWS * 2;
        for (long idx = (long)bx * 256 + tid; idx < total; idx += (long)PREP_MISC * 256) {
            long i = idx;
            if (i < H2) {
                float sc = g2[i] * rsqrtf(v2[i] + EPS);
                g_sh2[i] = b2[i] - m2[i] * sc;
                continue;
            }
            i -= H2;
            if (i < T_LEN) {
                int s = (int)i;
                int cnt = min(MSPAN, T_LEN - s);
                int ex = (s > 794) ? ((s - 794) * (s - 793)) / 2 : 0;
                int base = 16 * s - ex;
                for (int sp = 0; sp < cnt; sp++) {
                    g_sidx[base + sp] = s;
                    g_eidx[base + sp] = s + sp;
                }
                continue;
            }
            i -= T_LEN;
            if (i < MSPAN) {
                double c = 1.0;
                for (int k = 0; k <= (int)i; k++) c *= 0.9;
                g_coef[i] = (float)c;
                continue;
            }
            i -= MSPAN;
            if (i < CLEN + 1) {
                double c = 1.0;
                for (int k = 0; k < (int)i; k++) c *= 0.9;
                g_apow[i] = (float)c;
                continue;
            }
            i -= (CLEN + 1);
            out[i] = 0.f;   // zero output for atomicAdd accumulation
        }
    }
}

// ------- scan carries: 13-step serial recurrence per (b, dir, d) -------
__global__ void k_scan2() {
    const int d = threadIdx.x;      // 0..303
    const int b = blockIdx.x;
    const size_t base = (size_t)b * TPAD * DD;
    if (blockIdx.y == 0) {
        float carry = 0.f;
        const float a64 = g_apow[CLEN];
#pragma unroll 1
        for (int c = 0; c < NCHUNK; c++) {
            g_carryF[(b * NCHUNK + c) * DD + d] = carry;
            if (c < NCHUNK - 1) {
                float E = g_Ltmp[base + (size_t)((c + 1) * CLEN) * DD + d];
                carry = fmaf(a64, carry, E);
            }
        }
    } else {
        float carry = 0.f;
#pragma unroll 1
        for (int c = NCHUNK - 1; c >= 0; c--) {
            g_carryR[(b * NCHUNK + c) * DD + d] = carry;
            if (c > 0) {
                int len = min(CLEN, T_LEN - c * CLEN);
                float M = g_Mtmp[base + (size_t)(c * CLEN) * DD + d];
                carry = fmaf(g_apow[len], carry, M);
            }
        }
    }
}

// ------- apply carries + fp16 hi/lo split -> g_F/R arrays -------
constexpr int SC3_Q = DD / 4;   // 76 float4 groups per row
__global__ void __launch_bounds__(256) k_scan3() {
    int idx = blockIdx.x * 256 + threadIdx.x;
    const int total = 2 * BB * TPAD * SC3_Q;
    if (idx >= total) return;
    const int q = idx % SC3_Q;
    int rem = idx / SC3_Q;
    const int r = rem % TPAD;
    rem /= TPAD;
    const int b = rem % BB;
    const int dir = rem / BB;
    const int d = q * 4;
    const size_t ro = ((size_t)b * TPAD + r) * DD + d;

    float v[4];
    if (dir == 0) {
        __half zero = __float2half_rn(0.f);
        if (r == 0) {
            ((__half2*)&g_Fph[ro])[0] = __half2half2(zero);
            ((__half2*)&g_Fph[ro])[1] = __half2half2(zero);
            ((__half2*)&g_Fpl[ro])[0] = __half2half2(zero);
            ((__half2*)&g_Fpl[ro])[1] = __half2half2(zero);
            return;
        }
        int t = r - 1;
        int chunk = t >> 6;
        float p = g_apow[(t & 63) + 1];
        float4 L = *(const float4*)&g_Ltmp[ro];
        float4 C = *(const float4*)&g_carryF[(b * NCHUNK + chunk) * DD + d];
        v[0] = fmaf(p, C.x, L.x); v[1] = fmaf(p, C.y, L.y);
        v[2] = fmaf(p, C.z, L.z); v[3] = fmaf(p, C.w, L.w);
        __half2 h0 = __floats2half2_rn(v[0], v[1]);
        __half2 h1 = __floats2half2_rn(v[2], v[3]);
        float2 f0 = __half22float2(h0), f1 = __half22float2(h1);
        ((__half2*)&g_Fph[ro])[0] = h0;
        ((__half2*)&g_Fph[ro])[1] = h1;
        ((__half2*)&g_Fpl[ro])[0] = __floats2half2_rn(v[0] - f0.x, v[1] - f0.y);
        ((__half2*)&g_Fpl[ro])[1] = __floats2half2_rn(v[2] - f1.x, v[3] - f1.y);
    } else {
        __half zero = __float2half_rn(0.f);
        if (r == T_LEN) {
            ((__half2*)&g_Rph[ro])[0] = __half2half2(zero);
            ((__half2*)&g_Rph[ro])[1] = __half2half2(zero);
            ((__half2*)&g_Rpl[ro])[0] = __half2half2(zero);
            ((__half2*)&g_Rpl[ro])[1] = __half2half2(zero);
            return;
        }
        int t = r;
        int chunk = t >> 6;
        int end = min(T_LEN, (chunk + 1) << 6);
        float p = g_apow[end - t];
        float4 M = *(const float4*)&g_Mtmp[ro];
        float4 C = *(const float4*)&g_carryR[(b * NCHUNK + chunk) * DD + d];
        v[0] = fmaf(p, C.x, M.x); v[1] = fmaf(p, C.y, M.y);
        v[2] = fmaf(p, C.z, M.z); v[3] = fmaf(p, C.w, M.w);
        __half2 h0 = __floats2half2_rn(v[0], v[1]);
        __half2 h1 = __floats2half2_rn(v[2], v[3]);
        float2 f0 = __half22float2(h0), f1 = __half22float2(h1);
        ((__half2*)&g_Rph[ro])[0] = h0;
        ((__half2*)&g_Rph[ro])[1] = h1;
        ((__half2*)&g_Rpl[ro])[0] = __floats2half2_rn(v[0] - f0.x, v[1] - f0.y);
        ((__half2*)&g_Rpl[ro])[1] = __floats2half2_rn(v[2] - f1.x, v[3] - f1.y);
    }
}

// ---------- projections: fp16 mma, single launch; z2 = Fp@W1b + Rp@W1c -> PE ----
constexpr int PJ_SA = 48;
constexpr int PJ_SB = 272;
constexpr uint32_t PJ_AHF = 0;
constexpr uint32_t PJ_ALF = 6144;
constexpr uint32_t PJ_AHR = 12288;
constexpr uint32_t PJ_ALR = 18432;
constexpr uint32_t PJ_BB  = 24576;
constexpr uint32_t PJ_BC  = 28928;
constexpr uint32_t PJ_STAGE = 33280;
constexpr uint32_t PJ_SMEM = 2 * PJ_STAGE;   // 66560

__global__ void __launch_bounds__(256) k_proj() {
    extern __shared__ char sm[];
    const uint32_t sb = smem_u32(sm);
    const int z = blockIdx.z;
    const int m0 = blockIdx.x * 128;
    const int n0 = blockIdx.y * 128;
    const int tid = threadIdx.x;
    const int lane = tid & 31;
    const int w = tid >> 5;
    const int mw = w & 3;
    const int nw = w >> 2;

    __half* P = (z == 0) ? g_PX : (z == 1 ? g_PY : g_PE);

    const int amm = tid >> 1, aseg = tid & 1;
    const int am = (m0 + amm < MROWS) ? (m0 + amm) : 0;
    const int bkr = tid >> 4, bns = tid & 15;

    auto stage = [&](int cc) {
        const uint32_t st = sb + (uint32_t)(cc & 1) * PJ_STAGE;
        const int k0 = cc * 16;
        const size_t asrc = ((size_t)am * DD + k0 + aseg * 8);
        const uint32_t adst = (uint32_t)(amm * PJ_SA + aseg * 16);
        if (z < 2) {
            cp16(st + PJ_AHF + adst, g_Fph + asrc);
            cp16(st + PJ_ALF + adst, g_Fpl + asrc);
            const size_t bsrc = ((size_t)(z * DD + k0 + bkr)) * H1 + n0 + bns * 8;
            cp16(st + PJ_BB + (uint32_t)(bkr * PJ_SB + bns * 16), g_W1h3 + bsrc);
        } else {
            cp16(st + PJ_AHF + adst, g_Fph + asrc);
            cp16(st + PJ_ALF + adst, g_Fpl + asrc);
            cp16(st + PJ_AHR + adst, g_Rph + asrc);
            cp16(st + PJ_ALR + adst, g_Rpl + asrc);
            const size_t bsb = ((size_t)(1 * DD + k0 + bkr)) * H1 + n0 + bns * 8;
            const size_t bsc = ((size_t)(2 * DD + k0 + bkr)) * H1 + n0 + bns * 8;
            cp16(st + PJ_BB + (uint32_t)(bkr * PJ_SB + bns * 16), g_W1h3 + bsb);
            cp16(st + PJ_BC + (uint32_t)(bkr * PJ_SB + bns * 16), g_W1h3 + bsc);
        }
        cp_commit();
    };

    float acc[2][8][4];
#pragma unroll
    for (int i = 0; i < 2; i++)
#pragma unroll
        for (int j = 0; j < 8; j++)
#pragma unroll
            for (int c = 0; c < 4; c++) acc[i][j][c] = 0.f;

    const uint32_t aRel = (uint32_t)((mw * 32 + (lane & 15)) * PJ_SA + (lane >> 4) * 16);
    const uint32_t bRel = (uint32_t)((lane & 15) * PJ_SB + (nw * 64 + (lane >> 4) * 8) * 2);

    stage(0);
#pragma unroll 1
    for (int c = 0; c < 19; c++) {
        if (c < 18) { stage(c + 1); cp_wait<1>(); }
        else        { cp_wait<0>(); }
        __syncthreads();
        const uint32_t st = sb + (uint32_t)(c & 1) * PJ_STAGE;
        uint32_t ah[2][4], al[2][4];
        ldsm_x4(ah[0], st + PJ_AHF + aRel);
        ldsm_x4(ah[1], st + PJ_AHF + aRel + 16 * PJ_SA);
        ldsm_x4(al[0], st + PJ_ALF + aRel);
        ldsm_x4(al[1], st + PJ_ALF + aRel + 16 * PJ_SA);
#pragma unroll
        for (int g = 0; g < 4; g++) {
            uint32_t bh[4];
            ldsm_x4_t(bh, st + PJ_BB + bRel + g * 32);
#pragma unroll
            for (int m = 0; m < 2; m++) {
                mma16816(acc[m][2 * g],     ah[m], bh);
                mma16816(acc[m][2 * g + 1], ah[m], bh + 2);
                mma16816(acc[m][2 * g],     al[m], bh);
                mma16816(acc[m][2 * g + 1], al[m], bh + 2);
            }
        }
        if (z == 2) {
            uint32_t ahr[2][4], alr[2][4];
            ldsm_x4(ahr[0], st + PJ_AHR + aRel);
            ldsm_x4(ahr[1], st + PJ_AHR + aRel + 16 * PJ_SA);
            ldsm_x4(alr[0], st + PJ_ALR + aRel);
            ldsm_x4(alr[1], st + PJ_ALR + aRel + 16 * PJ_SA);
#pragma unroll
            for (int g = 0; g < 4; g++) {
                uint32_t bh[4];
                ldsm_x4_t(bh, st + PJ_BC + bRel + g * 32);
#pragma unroll
                for (int m = 0; m < 2; m++) {
                    mma16816(acc[m][2 * g],     ahr[m], bh);
                    mma16816(acc[m][2 * g + 1], ahr[m], bh + 2);
                    mma16816(acc[m][2 * g],     alr[m], bh);
                    mma16816(acc[m][2 * g + 1], alr[m], bh + 2);
                }
            }
        }
        __syncthreads();
    }

#pragma unroll
    for (int m = 0; m < 2; m++) {
        int row0 = m0 + mw * 32 + m * 16 + (lane >> 2);
#pragma unroll
        for (int h = 0; h < 2; h++) {
            int row = row0 + h * 8;
            if (row >= MROWS) continue;
            const int col = n0 + nw * 64 + (lane & 3) * 2;
            __half2* pr = (__half2*)&P[(size_t)row * H1 + col];
            const float* qr = (z == 0) ? &g_Pq[(row / TPAD) * H1 + col] : nullptr;
#pragma unroll
            for (int nf = 0; nf < 8; nf++) {
                float vx = acc[m][nf][2 * h];
                float vy = acc[m][nf][2 * h + 1];
                if (z == 0) {
                    vx += qr[nf * 8];
                    vy += qr[nf * 8 + 1];
                }
                pr[nf * 4] = __floats2half2_rn(vx, vy);
            }
        }
    }
}

// ---- main: fp16 mma GEMM2, M=64/N=256, 2 CTAs/SM (R10 structure) ----
constexpr int SA_STRIDE = 144;
constexpr int SB_STRIDE = 528;
constexpr uint32_t OFF_AH   = 0;                // 64*144 = 9216
constexpr uint32_t OFF_BH   = 9216;             // 64*528 = 33792
constexpr uint32_t STAGE_SZ = 43008;
constexpr uint32_t OFF_HDR  = 86016;
constexpr uint32_t OFF_OS   = OFF_HDR;
constexpr uint32_t OFF_OE   = OFF_HDR + 256;
constexpr uint32_t OFF_CF   = OFF_HDR + 512;
constexpr uint32_t OFF_W3A  = OFF_HDR + 768;
constexpr uint32_t OFF_W3B  = OFF_HDR + 1792;
constexpr uint32_t OFF_SH2  = OFF_HDR + 2816;
constexpr uint32_t OFF_RED  = OFF_HDR + 3840;
constexpr uint32_t SMEM_MAIN = OFF_HDR + 5888;  // 91904 (x2 CTAs/SM)

__global__ void __launch_bounds__(256, 2) k_main(const float* __restrict__ W3,
                                                 float* __restrict__ out) {
    extern __shared__ char sm[];
    const uint32_t sb = smem_u32(sm);
    const int tid = threadIdx.x;
    const int lane = tid & 31;
    const int w = tid >> 5;
    const int mw = w & 1;
    const int nw = w >> 1;
    const int batch = blockIdx.y;
    const int c0i = blockIdx.x * 64;
    const int n0 = blockIdx.z * 256;

    int*   sOS = (int*)(sm + OFF_OS);
    int*   sOE = (int*)(sm + OFF_OE);
    float* sCF = (float*)(sm + OFF_CF);
    float* sW3a = (float*)(sm + OFF_W3A);
    float* sW3b = (float*)(sm + OFF_W3B);
    float* sSh2 = (float*)(sm + OFF_SH2);
    float* sRed = (float*)(sm + OFF_RED);

    if (tid < 64) {
        int ci = c0i + tid;
        int offS = 0, offE = 0;
        float cf = 0.f;
        if (ci < NCAND) {
            int s = g_sidx[ci], e = g_eidx[ci];
            offS = (batch * TPAD + s) * H1;
            offE = (batch * TPAD + e + 1) * H1;
            cf = g_coef[e - s];
        }
        sOS[tid] = offS; sOE[tid] = offE; sCF[tid] = cf;
    }
    sW3a[tid] = W3[n0 + tid];
    sW3b[tid] = W3[H2 + n0 + tid];
    sSh2[tid] = g_sh2[n0 + tid];
    __syncthreads();

    const int wrow = w * 8;
    const int myOS = sOS[wrow + (lane & 7)];
    const int myOE = sOE[wrow + (lane & 7)];
    const float myCF = sCF[wrow + (lane & 7)];
    const bool uni = (__shfl_sync(0xffffffffu, myOS, 0) ==
                      __shfl_sync(0xffffffffu, myOS, 7));

    const int bkr = tid >> 5;
    const int bnc = tid & 31;

    const uint32_t aRel = OFF_AH + (uint32_t)((mw * 32 + (lane & 15)) * SA_STRIDE +
                                              ((lane >> 4) * 8) * 2);
    const uint32_t bRel = OFF_BH + (uint32_t)((lane & 15) * SB_STRIDE +
                                              (nw * 64 + (lane >> 4) * 8) * 2);

    float acc[2][8][4];
#pragma unroll
    for (int t = 0; t < 2; t++)
#pragma unroll
        for (int nf = 0; nf < 8; nf++)
#pragma unroll
            for (int c = 0; c < 4; c++) acc[t][nf][c] = 0.f;

    auto stage = [&](int cc) {
        const uint32_t stoff = (uint32_t)(cc & 1) * STAGE_SZ;
        const uint32_t st = sb + stoff;
        const __half* bsrc = &g_W2h16[(size_t)(cc * 64) * H2 + n0];
#pragma unroll
        for (int it = 0; it < 8; it++) {
            int kr = bkr + it * 8;
            cp16(st + OFF_BH + (uint32_t)(kr * SB_STRIDE + bnc * 16),
                 bsrc + (size_t)kr * H2 + bnc * 8);
        }
        cp_commit();
        const int kc = cc * 64 + 2 * lane;
        if (uni) {
            const int offS = __shfl_sync(0xffffffffu, myOS, 0);
            const float2 x = __half22float2(*(const __half2*)&g_PX[offS + kc]);
            const float2 y = __half22float2(*(const __half2*)&g_PY[offS + kc]);
#pragma unroll
            for (int rr = 0; rr < 8; rr++) {
                int offE = __shfl_sync(0xffffffffu, myOE, rr);
                float cf = __shfl_sync(0xffffffffu, myCF, rr);
                float2 e = __half22float2(*(const __half2*)&g_PE[offE + kc]);
                float v0 = fmaxf(x.x + e.x - cf * y.x, 0.f);
                float v1 = fmaxf(x.y + e.y - cf * y.y, 0.f);
                __half2 h = __floats2half2_rn(v0, v1);
                uint32_t ad = stoff + (uint32_t)((wrow + rr) * SA_STRIDE + lane * 4);
                *(uint32_t*)(sm + OFF_AH + ad) = h2u(h);
            }
        } else {
#pragma unroll
            for (int rr = 0; rr < 8; rr++) {
                int offS = __shfl_sync(0xffffffffu, myOS, rr);
                int offE = __shfl_sync(0xffffffffu, myOE, rr);
                float cf = __shfl_sync(0xffffffffu, myCF, rr);
                float2 x = __half22float2(*(const __half2*)&g_PX[offS + kc]);
                float2 y = __half22float2(*(const __half2*)&g_PY[offS + kc]);
                float2 e = __half22float2(*(const __half2*)&g_PE[offE + kc]);
                float v0 = fmaxf(x.x + e.x - cf * y.x, 0.f);
                float v1 = fmaxf(x.y + e.y - cf * y.y, 0.f);
                __half2 h = __floats2half2_rn(v0, v1);
                uint32_t ad = stoff + (uint32_t)((wrow + rr) * SA_STRIDE + lane * 4);
                *(uint32_t*)(sm + OFF_AH + ad) = h2u(h);
            }
        }
    };

    stage(0);

#pragma unroll 1
    for (int c = 0; c < 16; c++) {
        if (c < 15) { stage(c + 1); cp_wait<1>(); }
        else        { cp_wait<0>(); }
        __syncthreads();
        const uint32_t st = sb + (uint32_t)(c & 1) * STAGE_SZ;
#pragma unroll
        for (int s = 0; s < 4; s++) {
            const uint32_t ka = st + aRel + (uint32_t)(s * 32);
            uint32_t ah[2][4];
            ldsm_x4(ah[0], ka);
            ldsm_x4(ah[1], ka + 16 * SA_STRIDE);
            const uint32_t kbq = st + bRel + (uint32_t)(s * 16 * SB_STRIDE);
#pragma unroll
            for (int p = 0; p < 4; p++) {
                uint32_t bq[4];
                ldsm_x4_t(bq, kbq + p * 32);
                mma16816(acc[0][2 * p],     ah[0], bq);
                mma16816(acc[1][2 * p],     ah[1], bq);
                mma16816(acc[0][2 * p + 1], ah[0], bq + 2);
                mma16816(acc[1][2 * p + 1], ah[1], bq + 2);
            }
        }
        __syncthreads();
    }

    // ---- epilogue: relu(D + sh2) dot W3, reduce lanes + 4 N-groups, atomicAdd ----
    float sums[4][2];
#pragma unroll
    for (int q = 0; q < 4; q++) { sums[q][0] = 0.f; sums[q][1] = 0.f; }
#pragma unroll
    for (int t = 0; t < 2; t++) {
#pragma unroll
        for (int nf = 0; nf < 8; nf++) {
            int n = nw * 64 + nf * 8 + (lane & 3) * 2;
            float sh0 = sSh2[n], sh1 = sSh2[n + 1];
            float wa0 = sW3a[n], wa1 = sW3a[n + 1];
            float wb0 = sW3b[n], wb1 = sW3b[n + 1];
            float v0 = fmaxf(acc[t][nf][0] + sh0, 0.f);
            float v1 = fmaxf(acc[t][nf][1] + sh1, 0.f);
            float v2 = fmaxf(acc[t][nf][2] + sh0, 0.f);
            float v3 = fmaxf(acc[t][nf][3] + sh1, 0.f);
            sums[t * 2][0]     = fmaf(v0, wa0, fmaf(v1, wa1, sums[t * 2][0]));
            sums[t * 2][1]     = fmaf(v0, wb0, fmaf(v1, wb1, sums[t * 2][1]));
            sums[t * 2 + 1][0] = fmaf(v2, wa0, fmaf(v3, wa1, sums[t * 2 + 1][0]));
            sums[t * 2 + 1][1] = fmaf(v2, wb0, fmaf(v3, wb1, sums[t * 2 + 1][1]));
        }
    }
#pragma unroll
    for (int q = 0; q < 4; q++) {
#pragma unroll
        for (int o = 0; o < 2; o++) {
            sums[q][o] += __shfl_xor_sync(0xffffffffu, sums[q][o], 1);
            sums[q][o] += __shfl_xor_sync(0xffffffffu, sums[q][o], 2);
        }
    }
    __syncthreads();
    if ((lane & 3) == 0) {
#pragma unroll
        for (int q = 0; q < 4; q++) {
            int rloc = mw * 32 + (q >> 1) * 16 + (q & 1) * 8 + (lane >> 2);
            sRed[nw * 128 + rloc * 2 + 0] = sums[q][0];
            sRed[nw * 128 + rloc * 2 + 1] = sums[q][1];
        }
    }
    __syncthreads();
    if (tid < 128) {
        int rloc = tid >> 1, o = tid & 1;
        int ci = c0i + rloc;
        if (ci < NCAND) {
            float v = sRed[rloc * 2 + o] + sRed[128 + rloc * 2 + o] +
                      sRed[256 + rloc * 2 + o] + sRed[384 + rloc * 2 + o];
            atomicAdd(&out[(size_t)(batch * NCAND + ci) * 2 + o], v);
        }
    }
}

// ---------------- launch ----------------
extern "C" void kernel_launch(void* const* d_in, const int* in_sizes, int n_in,
                              void* d_out, int out_size) {
    (void)in_sizes; (void)n_in; (void)out_size;
    const float* doc = (const float*)d_in[0];
    const float* qe  = (const float*)d_in[1];
    const float* W1  = (const float*)d_in[2];
    const float* g1  = (const float*)d_in[3];
    const float* b1  = (const float*)d_in[4];
    const float* m1  = (const float*)d_in[5];
    const float* v1  = (const float*)d_in[6];
    const float* W2  = (const float*)d_in[7];
    const float* g2  = (const float*)d_in[8];
    const float* b2  = (const float*)d_in[9];
    const float* m2  = (const float*)d_in[10];
    const float* v2  = (const float*)d_in[11];
    const float* W3  = (const float*)d_in[12];
    float* out = (float*)d_out;

    cudaFuncSetAttribute(k_main, cudaFuncAttributeMaxDynamicSharedMemorySize, SMEM_MAIN);
    cudaFuncSetAttribute(k_proj, cudaFuncAttributeMaxDynamicSharedMemorySize, PJ_SMEM);

    k_prep<<<PREP_GRID, 256>>>(doc, qe, W1, g1, b1, m1, v1, W2, g2, b2, m2, v2, out);
    k_scan2<<<dim3(BB, 2), DD>>>();
    k_scan3<<<(2 * BB * TPAD * SC3_Q + 255) / 256, 256>>>();
    k_proj<<<dim3((MROWS + 127) / 128, H1 / 128, 3), 256, PJ_SMEM>>>();
    k_main<<<dim3((NCAND + 63) / 64, BB, 2), 256, SMEM_MAIN>>>(W3, out);
}

// round 13
// speedup vs baseline: 1.3292x; 1.0525x over previous
#include <cuda_runtime.h>
#include <cuda_fp16.h>
#include <cstdint>

#define ALPHA 0.9f
constexpr int T_LEN = 809;
constexpr int TPAD  = 810;
constexpr int DD    = 304;
constexpr int EE    = 300;
constexpr int LQ    = 30;
constexpr int BB    = 4;
constexpr int MSPAN = 16;
constexpr int H1    = 1024;
constexpr int H2    = 512;
constexpr int CIN   = 1212;
constexpr int NCAND = 12824;
constexpr int ROWS  = BB * NCAND;      // 51296
constexpr int MROWS = BB * TPAD;       // 3240
constexpr float EPS = 1e-5f;
constexpr int CLEN   = 64;
constexpr int NCHUNK = 13;

// ---------------- scratch ----------------
__device__ __align__(16) __half g_Fph[MROWS * DD];
__device__ __align__(16) __half g_Fpl[MROWS * DD];
__device__ __align__(16) __half g_Rph[MROWS * DD];
__device__ __align__(16) __half g_Rpl[MROWS * DD];
__device__ __align__(16) float g_Ltmp[MROWS * DD];
__device__ __align__(16) float g_Mtmp[MROWS * DD];
__device__ float g_carryF[BB * NCHUNK * DD];
__device__ float g_carryR[BB * NCHUNK * DD];
__device__ float g_apow[CLEN + 1];
__device__ __align__(16) __half g_W1h3[3 * DD * H1];
__device__ __align__(16) __half g_PX[MROWS * H1];   // fp16(PA + Pq)
__device__ __align__(16) __half g_PY[MROWS * H1];   // fp16(PB)
__device__ __align__(16) __half g_PE[MROWS * H1];   // fp16(PB + PC)
__device__ float g_Pq[BB * H1];
__device__ __align__(16) __half g_W2h16[H1 * H2];   // fp16(W2*sc2), [k][n]
__device__ float g_sh2[H2];
__device__ float g_coef[MSPAN];
__device__ int   g_sidx[NCAND];
__device__ int   g_eidx[NCAND];

// ---------------- helpers ----------------
__device__ __forceinline__ uint32_t smem_u32(const void* p) {
    uint32_t a;
    asm("{ .reg .u64 t; cvta.to.shared.u64 t, %1; cvt.u32.u64 %0, t; }" : "=r"(a) : "l"(p));
    return a;
}
__device__ __forceinline__ uint32_t h2u(__half2 h) { return *(uint32_t*)&h; }

__device__ __forceinline__ void ldsm_x4(uint32_t* r, uint32_t a) {
    asm volatile("ldmatrix.sync.aligned.m8n8.x4.shared.b16 {%0,%1,%2,%3}, [%4];"
                 : "=r"(r[0]), "=r"(r[1]), "=r"(r[2]), "=r"(r[3]) : "r"(a));
}
__device__ __forceinline__ void ldsm_x4_t(uint32_t* r, uint32_t a) {
    asm volatile("ldmatrix.sync.aligned.m8n8.x4.trans.shared.b16 {%0,%1,%2,%3}, [%4];"
                 : "=r"(r[0]), "=r"(r[1]), "=r"(r[2]), "=r"(r[3]) : "r"(a));
}
__device__ __forceinline__ void mma16816(float* d, const uint32_t* a, const uint32_t* b) {
    asm volatile(
        "mma.sync.aligned.m16n8k16.row.col.f32.f16.f16.f32 "
        "{%0,%1,%2,%3}, {%4,%5,%6,%7}, {%8,%9}, {%0,%1,%2,%3};"
        : "+f"(d[0]), "+f"(d[1]), "+f"(d[2]), "+f"(d[3])
        : "r"(a[0]), "r"(a[1]), "r"(a[2]), "r"(a[3]), "r"(b[0]), "r"(b[1]));
}
__device__ __forceinline__ void cp16(uint32_t dst, const void* src) {
    asm volatile("cp.async.cg.shared.global [%0], [%1], 16;" :: "r"(dst), "l"(src));
}
__device__ __forceinline__ void cp_commit() { asm volatile("cp.async.commit_group;"); }
template <int N> __device__ __forceinline__ void cp_wait() {
    asm volatile("cp.async.wait_group %0;" :: "n"(N));
}

// =================== fat prep kernel ==============
constexpr int PREP_W2   = 512;
constexpr int PREP_W1   = 960;
constexpr int PREP_SC1  = BB * 2 * NCHUNK;
constexpr int PREP_PQ   = 512;
constexpr int PREP_MISC = 64;
constexpr int PREP_GRID = PREP_W2 + PREP_W1 + PREP_SC1 + PREP_PQ + PREP_MISC;

__global__ void __launch_bounds__(256) k_prep(
    const float* __restrict__ doc, const float* __restrict__ Qe,
    const float* __restrict__ W1,
    const float* __restrict__ g1, const float* __restrict__ b1,
    const float* __restrict__ m1, const float* __restrict__ v1,
    const float* __restrict__ W2,
    const float* __restrict__ g2, const float* __restrict__ b2,
    const float* __restrict__ m2, const float* __restrict__ v2,
    float* __restrict__ out) {
    __shared__ float sh[32 * DD];
    int bx = blockIdx.x;
    const int tid = threadIdx.x;

    if (bx < PREP_W2) {
        float (*tl)[33] = (float(*)[33])sh;
        const int kt = bx & 31, nt = bx >> 5;
        const int k0 = kt * 32, n0 = nt * 32;
        const int tx = tid & 31, ty = tid >> 5;
#pragma unroll
        for (int it = 0; it < 4; it++)
            tl[ty + it * 8][tx] = W2[(size_t)(n0 + ty + it * 8) * H1 + k0 + tx];
        __syncthreads();
        const int n = n0 + tx;
        const float sc = g2[n] * rsqrtf(v2[n] + EPS);
#pragma unroll
        for (int it = 0; it < 4; it++) {
            int k = k0 + ty + it * 8;
            g_W2h16[(size_t)k * H2 + n] = __float2half_rn(tl[tx][ty + it * 8] * sc);
        }
        return;
    }
    bx -= PREP_W2;
    if (bx < PREP_W1) {
        float (*tl)[33] = (float(*)[33])sh;
        const int z = bx / 320;
        const int r = bx - z * 320;
        const int kt = r % 10, nt = r / 10;
        const int k0 = kt * 32, n0 = nt * 32;
        const int tx = tid & 31, ty = tid >> 5;
#pragma unroll
        for (int it = 0; it < 4; it++) {
            int n = n0 + ty + it * 8;
            int k = k0 + tx;
            tl[ty + it * 8][tx] = (k < DD) ? W1[(size_t)n * CIN + z * DD + k] : 0.f;
        }
        __syncthreads();
        const int n = n0 + tx;
        const float sc = g1[n] * rsqrtf(v1[n] + EPS);
#pragma unroll
        for (int it = 0; it < 4; it++) {
            int k = k0 + ty + it * 8;
            if (k >= DD) continue;
            g_W1h3[((size_t)(z * DD + k)) * H1 + n] =
                __float2half_rn(tl[tx][ty + it * 8] * sc);
        }
        return;
    }
    bx -= PREP_W1;
    if (bx < PREP_SC1) {
        const int dir = bx & 1;
        const int rest = bx >> 1;
        const int b = rest / NCHUNK;
        const int chunk = rest - b * NCHUNK;
        const int tstart = chunk * CLEN;
        const int tend = min(T_LEN, tstart + CLEN);
        const float* dp = doc + (size_t)b * T_LEN * DD;
        const int d0 = tid, d1 = tid + 256;
        const bool has1 = (d1 < DD);
        const size_t base = (size_t)b * TPAD * DD;
        if (dir == 0) {
            float a0 = 0.f, a1 = 0.f;
            for (int t0 = tstart; t0 < tend; t0 += 32) {
                int n = min(32, tend - t0);
                __syncthreads();
                for (int i = tid; i < n * DD; i += 256) sh[i] = dp[(size_t)t0 * DD + i];
                __syncthreads();
                for (int i = 0; i < n; i++) {
                    size_t ro = base + (size_t)(t0 + i + 1) * DD;
                    a0 = fmaf(ALPHA, a0, sh[i * DD + d0]);
                    g_Ltmp[ro + d0] = a0;
                    if (has1) {
                        a1 = fmaf(ALPHA, a1, sh[i * DD + d1]);
                        g_Ltmp[ro + d1] = a1;
                    }
                }
            }
        } else {
            float a0 = 0.f, a1 = 0.f;
            for (int hi = tend; hi > tstart; hi -= 32) {
                int lo = max(tstart, hi - 32);
                int n = hi - lo;
                __syncthreads();
                for (int i = tid; i < n * DD; i += 256) sh[i] = dp[(size_t)lo * DD + i];
                __syncthreads();
                for (int i = n - 1; i >= 0; i--) {
                    size_t ro = base + (size_t)(lo + i) * DD;
                    a0 = fmaf(ALPHA, a0, sh[i * DD + d0]);
                    g_Mtmp[ro + d0] = a0;
                    if (has1) {
                        a1 = fmaf(ALPHA, a1, sh[i * DD + d1]);
                        g_Mtmp[ro + d1] = a1;
                    }
                }
            }
        }
        return;
    }
    bx -= PREP_SC1;
    if (bx < PREP_PQ) {
        const int lane = tid & 31;
        const int gw = bx * 8 + (tid >> 5);
        const int j = gw & (H1 - 1);
        const int b = gw >> 10;
        const float sc = g1[j] * rsqrtf(v1[j] + EPS);
        const float* wrow = &W1[(size_t)j * CIN + 3 * DD];
        float dot = 0.f;
        for (int d = lane; d < EE; d += 32) {
            float qv = 0.f, p = 1.f;
#pragma unroll
            for (int t = LQ - 1; t >= 0; t--) {
                qv = fmaf(p, Qe[(b * LQ + t) * EE + d], qv);
                p *= ALPHA;
            }
            dot = fmaf(qv, wrow[d], dot);
        }
#pragma unroll
        for (int o = 16; o > 0; o >>= 1) dot += __shfl_xor_sync(0xffffffffu, dot, o);
        if (lane == 0) g_Pq[b * H1 + j] = b1[j] - m1[j] * sc + sc * dot;
        return;
    }
    bx -= PREP_PQ;
    {
        const long total = H2 + T_LEN + MSPAN + (CLEN + 1) + (long)ROWS * 2;
        for (long idx = (long)bx * 256 + tid; idx < total; idx += (long)PREP_MISC * 256) {
            long i = idx;
            if (i < H2) {
                float sc = g2[i] * rsqrtf(v2[i] + EPS);
                g_sh2[i] = b2[i] - m2[i] * sc;
                continue;
            }
            i -= H2;
            if (i < T_LEN) {
                int s = (int)i;
                int cnt = min(MSPAN, T_LEN - s);
                int ex = (s > 794) ? ((s - 794) * (s - 793)) / 2 : 0;
                int base = 16 * s - ex;
                for (int sp = 0; sp < cnt; sp++) {
                    g_sidx[base + sp] = s;
                    g_eidx[base + sp] = s + sp;
                }
                continue;
            }
            i -= T_LEN;
            if (i < MSPAN) {
                double c = 1.0;
                for (int k = 0; k <= (int)i; k++) c *= 0.9;
                g_coef[i] = (float)c;
                continue;
            }
            i -= MSPAN;
            if (i < CLEN + 1) {
                double c = 1.0;
                for (int k = 0; k < (int)i; k++) c *= 0.9;
                g_apow[i] = (float)c;
                continue;
            }
            i -= (CLEN + 1);
            out[i] = 0.f;
        }
    }
}

// ------- scan carries -------
__global__ void k_scan2() {
    const int d = threadIdx.x;
    const int b = blockIdx.x;
    const size_t base = (size_t)b * TPAD * DD;
    if (blockIdx.y == 0) {
        float carry = 0.f;
        const float a64 = g_apow[CLEN];
#pragma unroll 1
        for (int c = 0; c < NCHUNK; c++) {
            g_carryF[(b * NCHUNK + c) * DD + d] = carry;
            if (c < NCHUNK - 1) {
                float E = g_Ltmp[base + (size_t)((c + 1) * CLEN) * DD + d];
                carry = fmaf(a64, carry, E);
            }
        }
    } else {
        float carry = 0.f;
#pragma unroll 1
        for (int c = NCHUNK - 1; c >= 0; c--) {
            g_carryR[(b * NCHUNK + c) * DD + d] = carry;
            if (c > 0) {
                int len = min(CLEN, T_LEN - c * CLEN);
                float M = g_Mtmp[base + (size_t)(c * CLEN) * DD + d];
                carry = fmaf(g_apow[len], carry, M);
            }
        }
    }
}

// ------- apply carries + fp16 hi/lo split -------
constexpr int SC3_Q = DD / 4;
__global__ void __launch_bounds__(256) k_scan3() {
    int idx = blockIdx.x * 256 + threadIdx.x;
    const int total = 2 * BB * TPAD * SC3_Q;
    if (idx >= total) return;
    const int q = idx % SC3_Q;
    int rem = idx / SC3_Q;
    const int r = rem % TPAD;
    rem /= TPAD;
    const int b = rem % BB;
    const int dir = rem / BB;
    const int d = q * 4;
    const size_t ro = ((size_t)b * TPAD + r) * DD + d;

    float v[4];
    if (dir == 0) {
        __half zero = __float2half_rn(0.f);
        if (r == 0) {
            ((__half2*)&g_Fph[ro])[0] = __half2half2(zero);
            ((__half2*)&g_Fph[ro])[1] = __half2half2(zero);
            ((__half2*)&g_Fpl[ro])[0] = __half2half2(zero);
            ((__half2*)&g_Fpl[ro])[1] = __half2half2(zero);
            return;
        }
        int t = r - 1;
        int chunk = t >> 6;
        float p = g_apow[(t & 63) + 1];
        float4 L = *(const float4*)&g_Ltmp[ro];
        float4 C = *(const float4*)&g_carryF[(b * NCHUNK + chunk) * DD + d];
        v[0] = fmaf(p, C.x, L.x); v[1] = fmaf(p, C.y, L.y);
        v[2] = fmaf(p, C.z, L.z); v[3] = fmaf(p, C.w, L.w);
        __half2 h0 = __floats2half2_rn(v[0], v[1]);
        __half2 h1 = __floats2half2_rn(v[2], v[3]);
        float2 f0 = __half22float2(h0), f1 = __half22float2(h1);
        ((__half2*)&g_Fph[ro])[0] = h0;
        ((__half2*)&g_Fph[ro])[1] = h1;
        ((__half2*)&g_Fpl[ro])[0] = __floats2half2_rn(v[0] - f0.x, v[1] - f0.y);
        ((__half2*)&g_Fpl[ro])[1] = __floats2half2_rn(v[2] - f1.x, v[3] - f1.y);
    } else {
        __half zero = __float2half_rn(0.f);
        if (r == T_LEN) {
            ((__half2*)&g_Rph[ro])[0] = __half2half2(zero);
            ((__half2*)&g_Rph[ro])[1] = __half2half2(zero);
            ((__half2*)&g_Rpl[ro])[0] = __half2half2(zero);
            ((__half2*)&g_Rpl[ro])[1] = __half2half2(zero);
            return;
        }
        int t = r;
        int chunk = t >> 6;
        int end = min(T_LEN, (chunk + 1) << 6);
        float p = g_apow[end - t];
        float4 M = *(const float4*)&g_Mtmp[ro];
        float4 C = *(const float4*)&g_carryR[(b * NCHUNK + chunk) * DD + d];
        v[0] = fmaf(p, C.x, M.x); v[1] = fmaf(p, C.y, M.y);
        v[2] = fmaf(p, C.z, M.z); v[3] = fmaf(p, C.w, M.w);
        __half2 h0 = __floats2half2_rn(v[0], v[1]);
        __half2 h1 = __floats2half2_rn(v[2], v[3]);
        float2 f0 = __half22float2(h0), f1 = __half22float2(h1);
        ((__half2*)&g_Rph[ro])[0] = h0;
        ((__half2*)&g_Rph[ro])[1] = h1;
        ((__half2*)&g_Rpl[ro])[0] = __floats2half2_rn(v[0] - f0.x, v[1] - f0.y);
        ((__half2*)&g_Rpl[ro])[1] = __floats2half2_rn(v[2] - f1.x, v[3] - f1.y);
    }
}

// ---------- projections: fp16 mma; z2 = Fp@W1b + Rp@W1c -> PE ----
constexpr int PJ_SA = 48;
constexpr int PJ_SB = 272;
constexpr uint32_t PJ_AHF = 0;
constexpr uint32_t PJ_ALF = 6144;
constexpr uint32_t PJ_AHR = 12288;
constexpr uint32_t PJ_ALR = 18432;
constexpr uint32_t PJ_BB  = 24576;
constexpr uint32_t PJ_BC  = 28928;
constexpr uint32_t PJ_STAGE = 33280;
constexpr uint32_t PJ_SMEM = 2 * PJ_STAGE;

__global__ void __launch_bounds__(256) k_proj() {
    extern __shared__ char sm[];
    const uint32_t sb = smem_u32(sm);
    const int z = blockIdx.z;
    const int m0 = blockIdx.x * 128;
    const int n0 = blockIdx.y * 128;
    const int tid = threadIdx.x;
    const int lane = tid & 31;
    const int w = tid >> 5;
    const int mw = w & 3;
    const int nw = w >> 2;

    __half* P = (z == 0) ? g_PX : (z == 1 ? g_PY : g_PE);

    const int amm = tid >> 1, aseg = tid & 1;
    const int am = (m0 + amm < MROWS) ? (m0 + amm) : 0;
    const int bkr = tid >> 4, bns = tid & 15;

    auto stage = [&](int cc) {
        const uint32_t st = sb + (uint32_t)(cc & 1) * PJ_STAGE;
        const int k0 = cc * 16;
        const size_t asrc = ((size_t)am * DD + k0 + aseg * 8);
        const uint32_t adst = (uint32_t)(amm * PJ_SA + aseg * 16);
        if (z < 2) {
            cp16(st + PJ_AHF + adst, g_Fph + asrc);
            cp16(st + PJ_ALF + adst, g_Fpl + asrc);
            const size_t bsrc = ((size_t)(z * DD + k0 + bkr)) * H1 + n0 + bns * 8;
            cp16(st + PJ_BB + (uint32_t)(bkr * PJ_SB + bns * 16), g_W1h3 + bsrc);
        } else {
            cp16(st + PJ_AHF + adst, g_Fph + asrc);
            cp16(st + PJ_ALF + adst, g_Fpl + asrc);
            cp16(st + PJ_AHR + adst, g_Rph + asrc);
            cp16(st + PJ_ALR + adst, g_Rpl + asrc);
            const size_t bsb = ((size_t)(1 * DD + k0 + bkr)) * H1 + n0 + bns * 8;
            const size_t bsc = ((size_t)(2 * DD + k0 + bkr)) * H1 + n0 + bns * 8;
            cp16(st + PJ_BB + (uint32_t)(bkr * PJ_SB + bns * 16), g_W1h3 + bsb);
            cp16(st + PJ_BC + (uint32_t)(bkr * PJ_SB + bns * 16), g_W1h3 + bsc);
        }
        cp_commit();
    };

    float acc[2][8][4];
#pragma unroll
    for (int i = 0; i < 2; i++)
#pragma unroll
        for (int j = 0; j < 8; j++)
#pragma unroll
            for (int c = 0; c < 4; c++) acc[i][j][c] = 0.f;

    const uint32_t aRel = (uint32_t)((mw * 32 + (lane & 15)) * PJ_SA + (lane >> 4) * 16);
    const uint32_t bRel = (uint32_t)((lane & 15) * PJ_SB + (nw * 64 + (lane >> 4) * 8) * 2);

    stage(0);
#pragma unroll 1
    for (int c = 0; c < 19; c++) {
        if (c < 18) { stage(c + 1); cp_wait<1>(); }
        else        { cp_wait<0>(); }
        __syncthreads();
        const uint32_t st = sb + (uint32_t)(c & 1) * PJ_STAGE;
        uint32_t ah[2][4], al[2][4];
        ldsm_x4(ah[0], st + PJ_AHF + aRel);
        ldsm_x4(ah[1], st + PJ_AHF + aRel + 16 * PJ_SA);
        ldsm_x4(al[0], st + PJ_ALF + aRel);
        ldsm_x4(al[1], st + PJ_ALF + aRel + 16 * PJ_SA);
#pragma unroll
        for (int g = 0; g < 4; g++) {
            uint32_t bh[4];
            ldsm_x4_t(bh, st + PJ_BB + bRel + g * 32);
#pragma unroll
            for (int m = 0; m < 2; m++) {
                mma16816(acc[m][2 * g],     ah[m], bh);
                mma16816(acc[m][2 * g + 1], ah[m], bh + 2);
                mma16816(acc[m][2 * g],     al[m], bh);
                mma16816(acc[m][2 * g + 1], al[m], bh + 2);
            }
        }
        if (z == 2) {
            uint32_t ahr[2][4], alr[2][4];
            ldsm_x4(ahr[0], st + PJ_AHR + aRel);
            ldsm_x4(ahr[1], st + PJ_AHR + aRel + 16 * PJ_SA);
            ldsm_x4(alr[0], st + PJ_ALR + aRel);
            ldsm_x4(alr[1], st + PJ_ALR + aRel + 16 * PJ_SA);
#pragma unroll
            for (int g = 0; g < 4; g++) {
                uint32_t bh[4];
                ldsm_x4_t(bh, st + PJ_BC + bRel + g * 32);
#pragma unroll
                for (int m = 0; m < 2; m++) {
                    mma16816(acc[m][2 * g],     ahr[m], bh);
                    mma16816(acc[m][2 * g + 1], ahr[m], bh + 2);
                    mma16816(acc[m][2 * g],     alr[m], bh);
                    mma16816(acc[m][2 * g + 1], alr[m], bh + 2);
                }
            }
        }
        __syncthreads();
    }

#pragma unroll
    for (int m = 0; m < 2; m++) {
        int row0 = m0 + mw * 32 + m * 16 + (lane >> 2);
#pragma unroll
        for (int h = 0; h < 2; h++) {
            int row = row0 + h * 8;
            if (row >= MROWS) continue;
            const int col = n0 + nw * 64 + (lane & 3) * 2;
            __half2* pr = (__half2*)&P[(size_t)row * H1 + col];
            const float* qr = (z == 0) ? &g_Pq[(row / TPAD) * H1 + col] : nullptr;
#pragma unroll
            for (int nf = 0; nf < 8; nf++) {
                float vx = acc[m][nf][2 * h];
                float vy = acc[m][nf][2 * h + 1];
                if (z == 0) {
                    vx += qr[nf * 8];
                    vy += qr[nf * 8 + 1];
                }
                pr[nf * 4] = __floats2half2_rn(vx, vy);
            }
        }
    }
}

// ---- main: fp16 mma GEMM2, register-pipelined A-gen (ld -> mma -> cvt) ----
constexpr int SA_STRIDE = 144;
constexpr int SB_STRIDE = 528;
constexpr uint32_t OFF_AH   = 0;
constexpr uint32_t OFF_BH   = 9216;
constexpr uint32_t STAGE_SZ = 43008;
constexpr uint32_t OFF_HDR  = 86016;
constexpr uint32_t OFF_OS   = OFF_HDR;
constexpr uint32_t OFF_OE   = OFF_HDR + 256;
constexpr uint32_t OFF_CF   = OFF_HDR + 512;
constexpr uint32_t OFF_W3A  = OFF_HDR + 768;
constexpr uint32_t OFF_W3B  = OFF_HDR + 1792;
constexpr uint32_t OFF_SH2  = OFF_HDR + 2816;
constexpr uint32_t OFF_RED  = OFF_HDR + 3840;
constexpr uint32_t SMEM_MAIN = OFF_HDR + 5888;

__global__ void __launch_bounds__(256, 2) k_main(const float* __restrict__ W3,
                                                 float* __restrict__ out) {
    extern __shared__ char sm[];
    const uint32_t sb = smem_u32(sm);
    const int tid = threadIdx.x;
    const int lane = tid & 31;
    const int w = tid >> 5;
    const int mw = w & 1;
    const int nw = w >> 1;
    const int batch = blockIdx.y;
    const int c0i = blockIdx.x * 64;
    const int n0 = blockIdx.z * 256;

    int*   sOS = (int*)(sm + OFF_OS);
    int*   sOE = (int*)(sm + OFF_OE);
    float* sCF = (float*)(sm + OFF_CF);
    float* sW3a = (float*)(sm + OFF_W3A);
    float* sW3b = (float*)(sm + OFF_W3B);
    float* sSh2 = (float*)(sm + OFF_SH2);
    float* sRed = (float*)(sm + OFF_RED);

    if (tid < 64) {
        int ci = c0i + tid;
        int offS = 0, offE = 0;
        float cf = 0.f;
        if (ci < NCAND) {
            int s = g_sidx[ci], e = g_eidx[ci];
            offS = (batch * TPAD + s) * H1;
            offE = (batch * TPAD + e + 1) * H1;
            cf = g_coef[e - s];
        }
        sOS[tid] = offS; sOE[tid] = offE; sCF[tid] = cf;
    }
    sW3a[tid] = W3[n0 + tid];
    sW3b[tid] = W3[H2 + n0 + tid];
    sSh2[tid] = g_sh2[n0 + tid];
    __syncthreads();

    const int wrow = w * 8;
    const int myOS = sOS[wrow + (lane & 7)];
    const int myOE = sOE[wrow + (lane & 7)];
    const float myCF = sCF[wrow + (lane & 7)];
    const bool uni = (__shfl_sync(0xffffffffu, myOS, 0) ==
                      __shfl_sync(0xffffffffu, myOS, 7));
    const int offSu = __shfl_sync(0xffffffffu, myOS, 0);
    int offEr[8];
    float cfr[8];
#pragma unroll
    for (int rr = 0; rr < 8; rr++) {
        offEr[rr] = __shfl_sync(0xffffffffu, myOE, rr);
        cfr[rr] = __shfl_sync(0xffffffffu, myCF, rr);
    }
    int offSr[8];
#pragma unroll
    for (int rr = 0; rr < 8; rr++) offSr[rr] = __shfl_sync(0xffffffffu, myOS, rr);

    const int bkr = tid >> 5;
    const int bnc = tid & 31;

    const uint32_t aRel = OFF_AH + (uint32_t)((mw * 32 + (lane & 15)) * SA_STRIDE +
                                              ((lane >> 4) * 8) * 2);
    const uint32_t bRel = OFF_BH + (uint32_t)((lane & 15) * SB_STRIDE +
                                              (nw * 64 + (lane >> 4) * 8) * 2);

    float acc[2][8][4];
#pragma unroll
    for (int t = 0; t < 2; t++)
#pragma unroll
        for (int nf = 0; nf < 8; nf++)
#pragma unroll
            for (int c = 0; c < 4; c++) acc[t][nf][c] = 0.f;

    auto issueB = [&](int cc) {
        const uint32_t st = sb + (uint32_t)(cc & 1) * STAGE_SZ;
        const __half* bsrc = &g_W2h16[(size_t)(cc * 64) * H2 + n0];
#pragma unroll
        for (int it = 0; it < 8; it++) {
            int kr = bkr + it * 8;
            cp16(st + OFF_BH + (uint32_t)(kr * SB_STRIDE + bnc * 16),
                 bsrc + (size_t)kr * H2 + bnc * 8);
        }
        cp_commit();
    };

    __half2 er[8], xr[8], yr[8];   // raw A inputs in flight (non-uni uses xr/yr arrays)
    auto ldA = [&](int cc) {
        const int kc = cc * 64 + 2 * lane;
#pragma unroll
        for (int rr = 0; rr < 8; rr++)
            er[rr] = *(const __half2*)&g_PE[offEr[rr] + kc];
        if (uni) {
            xr[0] = *(const __half2*)&g_PX[offSu + kc];
            yr[0] = *(const __half2*)&g_PY[offSu + kc];
        } else {
#pragma unroll
            for (int rr = 0; rr < 8; rr++) {
                xr[rr] = *(const __half2*)&g_PX[offSr[rr] + kc];
                yr[rr] = *(const __half2*)&g_PY[offSr[rr] + kc];
            }
        }
    };
    auto cvtStore = [&](int cc) {
        const uint32_t stoff = (uint32_t)(cc & 1) * STAGE_SZ;
        if (uni) {
            float2 x = __half22float2(xr[0]);
            float2 y = __half22float2(yr[0]);
#pragma unroll
            for (int rr = 0; rr < 8; rr++) {
                float2 e = __half22float2(er[rr]);
                float v0 = fmaxf(x.x + e.x - cfr[rr] * y.x, 0.f);
                float v1 = fmaxf(x.y + e.y - cfr[rr] * y.y, 0.f);
                __half2 h = __floats2half2_rn(v0, v1);
                uint32_t ad = stoff + (uint32_t)((wrow + rr) * SA_STRIDE + lane * 4);
                *(uint32_t*)(sm + OFF_AH + ad) = h2u(h);
            }
        } else {
#pragma unroll
            for (int rr = 0; rr < 8; rr++) {
                float2 x = __half22float2(xr[rr]);
                float2 y = __half22float2(yr[rr]);
                float2 e = __half22float2(er[rr]);
                float v0 = fmaxf(x.x + e.x - cfr[rr] * y.x, 0.f);
                float v1 = fmaxf(x.y + e.y - cfr[rr] * y.y, 0.f);
                __half2 h = __floats2half2_rn(v0, v1);
                uint32_t ad = stoff + (uint32_t)((wrow + rr) * SA_STRIDE + lane * 4);
                *(uint32_t*)(sm + OFF_AH + ad) = h2u(h);
            }
        }
    };

    // prologue: chunk 0
    issueB(0);
    ldA(0);
    cvtStore(0);
    cp_wait<0>();
    __syncthreads();

#pragma unroll 1
    for (int c = 0; c < 16; c++) {
        if (c < 15) {
            issueB(c + 1);   // cp.async into buf (c+1)&1
            ldA(c + 1);      // LDGs in flight; latency covered by mma(c)
        }
        const uint32_t st = sb + (uint32_t)(c & 1) * STAGE_SZ;
#pragma unroll
        for (int s = 0; s < 4; s++) {
            const uint32_t ka = st + aRel + (uint32_t)(s * 32);
            uint32_t ah[2][4];
            ldsm_x4(ah[0], ka);
            ldsm_x4(ah[1], ka + 16 * SA_STRIDE);
            const uint32_t kbq = st + bRel + (uint32_t)(s * 16 * SB_STRIDE);
#pragma unroll
            for (int p = 0; p < 4; p++) {
                uint32_t bq[4];
                ldsm_x4_t(bq, kbq + p * 32);
                mma16816(acc[0][2 * p],     ah[0], bq);
                mma16816(acc[1][2 * p],     ah[1], bq);
                mma16816(acc[0][2 * p + 1], ah[0], bq + 2);
                mma16816(acc[1][2 * p + 1], ah[1], bq + 2);
            }
        }
        if (c < 15) {
            cvtStore(c + 1);   // writes buf (c+1)&1; its prior readers (mma(c-1)) all passed last sync
            cp_wait<0>();      // B(c+1) landed
            __syncthreads();   // publish A(c+1) + B(c+1)
        }
    }

    // ---- epilogue: relu(D + sh2) dot W3, reduce lanes + 4 N-groups, atomicAdd ----
    float sums[4][2];
#pragma unroll
    for (int q = 0; q < 4; q++) { sums[q][0] = 0.f; sums[q][1] = 0.f; }
#pragma unroll
    for (int t = 0; t < 2; t++) {
#pragma unroll
        for (int nf = 0; nf < 8; nf++) {
            int n = nw * 64 + nf * 8 + (lane & 3) * 2;
            float sh0 = sSh2[n], sh1 = sSh2[n + 1];
            float wa0 = sW3a[n], wa1 = sW3a[n + 1];
            float wb0 = sW3b[n], wb1 = sW3b[n + 1];
            float v0 = fmaxf(acc[t][nf][0] + sh0, 0.f);
            float v1 = fmaxf(acc[t][nf][1] + sh1, 0.f);
            float v2 = fmaxf(acc[t][nf][2] + sh0, 0.f);
            float v3 = fmaxf(acc[t][nf][3] + sh1, 0.f);
            sums[t * 2][0]     = fmaf(v0, wa0, fmaf(v1, wa1, sums[t * 2][0]));
            sums[t * 2][1]     = fmaf(v0, wb0, fmaf(v1, wb1, sums[t * 2][1]));
            sums[t * 2 + 1][0] = fmaf(v2, wa0, fmaf(v3, wa1, sums[t * 2 + 1][0]));
            sums[t * 2 + 1][1] = fmaf(v2, wb0, fmaf(v3, wb1, sums[t * 2 + 1][1]));
        }
    }
#pragma unroll
    for (int q = 0; q < 4; q++) {
#pragma unroll
        for (int o = 0; o < 2; o++) {
            sums[q][o] += __shfl_xor_sync(0xffffffffu, sums[q][o], 1);
            sums[q][o] += __shfl_xor_sync(0xffffffffu, sums[q][o], 2);
        }
    }
    __syncthreads();
    if ((lane & 3) == 0) {
#pragma unroll
        for (int q = 0; q < 4; q++) {
            int rloc = mw * 32 + (q >> 1) * 16 + (q & 1) * 8 + (lane >> 2);
            sRed[nw * 128 + rloc * 2 + 0] = sums[q][0];
            sRed[nw * 128 + rloc * 2 + 1] = sums[q][1];
        }
    }
    __syncthreads();
    if (tid < 128) {
        int rloc = tid >> 1, o = tid & 1;
        int ci = c0i + rloc;
        if (ci < NCAND) {
            float v = sRed[rloc * 2 + o] + sRed[128 + rloc * 2 + o] +
                      sRed[256 + rloc * 2 + o] + sRed[384 + rloc * 2 + o];
            atomicAdd(&out[(size_t)(batch * NCAND + ci) * 2 + o], v);
        }
    }
}

// ---------------- launch ----------------
extern "C" void kernel_launch(void* const* d_in, const int* in_sizes, int n_in,
                              void* d_out, int out_size) {
    (void)in_sizes; (void)n_in; (void)out_size;
    const float* doc = (const float*)d_in[0];
    const float* qe  = (const float*)d_in[1];
    const float* W1  = (const float*)d_in[2];
    const float* g1  = (const float*)d_in[3];
    const float* b1  = (const float*)d_in[4];
    const float* m1  = (const float*)d_in[5];
    const float* v1  = (const float*)d_in[6];
    const float* W2  = (const float*)d_in[7];
    const float* g2  = (const float*)d_in[8];
    const float* b2  = (const float*)d_in[9];
    const float* m2  = (const float*)d_in[10];
    const float* v2  = (const float*)d_in[11];
    const float* W3  = (const float*)d_in[12];
    float* out = (float*)d_out;

    cudaFuncSetAttribute(k_main, cudaFuncAttributeMaxDynamicSharedMemorySize, SMEM_MAIN);
    cudaFuncSetAttribute(k_proj, cudaFuncAttributeMaxDynamicSharedMemorySize, PJ_SMEM);

    k_prep<<<PREP_GRID, 256>>>(doc, qe, W1, g1, b1, m1, v1, W2, g2, b2, m2, v2, out);
    k_scan2<<<dim3(BB, 2), DD>>>();
    k_scan3<<<(2 * BB * TPAD * SC3_Q + 255) / 256, 256>>>();
    k_proj<<<dim3((MROWS + 127) / 128, H1 / 128, 3), 256, PJ_SMEM>>>();
    k_main<<<dim3((NCAND + 63) / 64, BB, 2), 256, SMEM_MAIN>>>(W3, out);
}

// round 14
// speedup vs baseline: 1.3382x; 1.0068x over previous
#include <cuda_runtime.h>
#include <cuda_fp16.h>
#include <cstdint>

#define ALPHA 0.9f
constexpr int T_LEN = 809;
constexpr int TPAD  = 810;
constexpr int DD    = 304;
constexpr int EE    = 300;
constexpr int LQ    = 30;
constexpr int BB    = 4;
constexpr int MSPAN = 16;
constexpr int H1    = 1024;
constexpr int H2    = 512;
constexpr int CIN   = 1212;
constexpr int NCAND = 12824;
constexpr int ROWS  = BB * NCAND;      // 51296
constexpr int MROWS = BB * TPAD;       // 3240
constexpr float EPS = 1e-5f;
constexpr int CLEN   = 64;
constexpr int NCHUNK = 13;
constexpr int KPAD   = 320;            // W1 k-dim padded (zeros 304..319)

// ---------------- scratch ----------------
__device__ __align__(16) __half g_Fph[MROWS * DD + 16];   // +16 zero tail (K=32 over-read)
__device__ __align__(16) __half g_Fpl[MROWS * DD + 16];
__device__ __align__(16) __half g_Rph[MROWS * DD + 16];
__device__ __align__(16) __half g_Rpl[MROWS * DD + 16];
__device__ __align__(16) float g_Ltmp[MROWS * DD];
__device__ __align__(16) float g_Mtmp[MROWS * DD];
__device__ float g_carryF[BB * NCHUNK * DD];
__device__ float g_carryR[BB * NCHUNK * DD];
__device__ float g_apow[CLEN + 1];
__device__ __align__(16) __half g_W1h3[3 * KPAD * H1];    // [z][kpad][n], zero pad rows
__device__ __align__(16) __half g_PX[MROWS * H1];
__device__ __align__(16) __half g_PY[MROWS * H1];
__device__ __align__(16) __half g_PE[MROWS * H1];
__device__ float g_Pq[BB * H1];
__device__ __align__(16) __half g_W2h16[H1 * H2];
__device__ float g_sh2[H2];
__device__ float g_coef[MSPAN];
__device__ int   g_sidx[NCAND];
__device__ int   g_eidx[NCAND];

// ---------------- helpers ----------------
__device__ __forceinline__ uint32_t smem_u32(const void* p) {
    uint32_t a;
    asm("{ .reg .u64 t; cvta.to.shared.u64 t, %1; cvt.u32.u64 %0, t; }" : "=r"(a) : "l"(p));
    return a;
}
__device__ __forceinline__ uint32_t h2u(__half2 h) { return *(uint32_t*)&h; }

__device__ __forceinline__ void ldsm_x4(uint32_t* r, uint32_t a) {
    asm volatile("ldmatrix.sync.aligned.m8n8.x4.shared.b16 {%0,%1,%2,%3}, [%4];"
                 : "=r"(r[0]), "=r"(r[1]), "=r"(r[2]), "=r"(r[3]) : "r"(a));
}
__device__ __forceinline__ void ldsm_x4_t(uint32_t* r, uint32_t a) {
    asm volatile("ldmatrix.sync.aligned.m8n8.x4.trans.shared.b16 {%0,%1,%2,%3}, [%4];"
                 : "=r"(r[0]), "=r"(r[1]), "=r"(r[2]), "=r"(r[3]) : "r"(a));
}
__device__ __forceinline__ void mma16816(float* d, const uint32_t* a, const uint32_t* b) {
    asm volatile(
        "mma.sync.aligned.m16n8k16.row.col.f32.f16.f16.f32 "
        "{%0,%1,%2,%3}, {%4,%5,%6,%7}, {%8,%9}, {%0,%1,%2,%3};"
        : "+f"(d[0]), "+f"(d[1]), "+f"(d[2]), "+f"(d[3])
        : "r"(a[0]), "r"(a[1]), "r"(a[2]), "r"(a[3]), "r"(b[0]), "r"(b[1]));
}
__device__ __forceinline__ void cp16(uint32_t dst, const void* src) {
    asm volatile("cp.async.cg.shared.global [%0], [%1], 16;" :: "r"(dst), "l"(src));
}
__device__ __forceinline__ void cp_commit() { asm volatile("cp.async.commit_group;"); }
template <int N> __device__ __forceinline__ void cp_wait() {
    asm volatile("cp.async.wait_group %0;" :: "n"(N));
}

// =================== fat prep kernel ==============
constexpr int PREP_W2   = 512;
constexpr int PREP_W1   = 960;    // 3 z x 10 k-tiles(0..319) x 32 n-tiles
constexpr int PREP_SC1  = BB * 2 * NCHUNK;
constexpr int PREP_PQ   = 512;
constexpr int PREP_MISC = 64;
constexpr int PREP_GRID = PREP_W2 + PREP_W1 + PREP_SC1 + PREP_PQ + PREP_MISC;

__global__ void __launch_bounds__(256) k_prep(
    const float* __restrict__ doc, const float* __restrict__ Qe,
    const float* __restrict__ W1,
    const float* __restrict__ g1, const float* __restrict__ b1,
    const float* __restrict__ m1, const float* __restrict__ v1,
    const float* __restrict__ W2,
    const float* __restrict__ g2, const float* __restrict__ b2,
    const float* __restrict__ m2, const float* __restrict__ v2,
    float* __restrict__ out) {
    __shared__ float sh[32 * DD];
    int bx = blockIdx.x;
    const int tid = threadIdx.x;

    if (bx < PREP_W2) {
        float (*tl)[33] = (float(*)[33])sh;
        const int kt = bx & 31, nt = bx >> 5;
        const int k0 = kt * 32, n0 = nt * 32;
        const int tx = tid & 31, ty = tid >> 5;
#pragma unroll
        for (int it = 0; it < 4; it++)
            tl[ty + it * 8][tx] = W2[(size_t)(n0 + ty + it * 8) * H1 + k0 + tx];
        __syncthreads();
        const int n = n0 + tx;
        const float sc = g2[n] * rsqrtf(v2[n] + EPS);
#pragma unroll
        for (int it = 0; it < 4; it++) {
            int k = k0 + ty + it * 8;
            g_W2h16[(size_t)k * H2 + n] = __float2half_rn(tl[tx][ty + it * 8] * sc);
        }
        return;
    }
    bx -= PREP_W2;
    if (bx < PREP_W1) {
        float (*tl)[33] = (float(*)[33])sh;
        const int z = bx / 320;
        const int r = bx - z * 320;
        const int kt = r % 10, nt = r / 10;
        const int k0 = kt * 32, n0 = nt * 32;
        const int tx = tid & 31, ty = tid >> 5;
#pragma unroll
        for (int it = 0; it < 4; it++) {
            int n = n0 + ty + it * 8;
            int k = k0 + tx;
            tl[ty + it * 8][tx] = (k < DD) ? W1[(size_t)n * CIN + z * DD + k] : 0.f;
        }
        __syncthreads();
        const int n = n0 + tx;
        const float sc = g1[n] * rsqrtf(v1[n] + EPS);
#pragma unroll
        for (int it = 0; it < 4; it++) {
            int k = k0 + ty + it * 8;   // 0..319, pad rows get zeros
            g_W1h3[((size_t)(z * KPAD + k)) * H1 + n] =
                __float2half_rn(tl[tx][ty + it * 8] * sc);
        }
        return;
    }
    bx -= PREP_W1;
    if (bx < PREP_SC1) {
        const int dir = bx & 1;
        const int rest = bx >> 1;
        const int b = rest / NCHUNK;
        const int chunk = rest - b * NCHUNK;
        const int tstart = chunk * CLEN;
        const int tend = min(T_LEN, tstart + CLEN);
        const float* dp = doc + (size_t)b * T_LEN * DD;
        const int d0 = tid, d1 = tid + 256;
        const bool has1 = (d1 < DD);
        const size_t base = (size_t)b * TPAD * DD;
        if (dir == 0) {
            float a0 = 0.f, a1 = 0.f;
            for (int t0 = tstart; t0 < tend; t0 += 32) {
                int n = min(32, tend - t0);
                __syncthreads();
                for (int i = tid; i < n * DD; i += 256) sh[i] = dp[(size_t)t0 * DD + i];
                __syncthreads();
                for (int i = 0; i < n; i++) {
                    size_t ro = base + (size_t)(t0 + i + 1) * DD;
                    a0 = fmaf(ALPHA, a0, sh[i * DD + d0]);
                    g_Ltmp[ro + d0] = a0;
                    if (has1) {
                        a1 = fmaf(ALPHA, a1, sh[i * DD + d1]);
                        g_Ltmp[ro + d1] = a1;
                    }
                }
            }
        } else {
            float a0 = 0.f, a1 = 0.f;
            for (int hi = tend; hi > tstart; hi -= 32) {
                int lo = max(tstart, hi - 32);
                int n = hi - lo;
                __syncthreads();
                for (int i = tid; i < n * DD; i += 256) sh[i] = dp[(size_t)lo * DD + i];
                __syncthreads();
                for (int i = n - 1; i >= 0; i--) {
                    size_t ro = base + (size_t)(lo + i) * DD;
                    a0 = fmaf(ALPHA, a0, sh[i * DD + d0]);
                    g_Mtmp[ro + d0] = a0;
                    if (has1) {
                        a1 = fmaf(ALPHA, a1, sh[i * DD + d1]);
                        g_Mtmp[ro + d1] = a1;
                    }
                }
            }
        }
        return;
    }
    bx -= PREP_SC1;
    if (bx < PREP_PQ) {
        const int lane = tid & 31;
        const int gw = bx * 8 + (tid >> 5);
        const int j = gw & (H1 - 1);
        const int b = gw >> 10;
        const float sc = g1[j] * rsqrtf(v1[j] + EPS);
        const float* wrow = &W1[(size_t)j * CIN + 3 * DD];
        float dot = 0.f;
        for (int d = lane; d < EE; d += 32) {
            float qv = 0.f, p = 1.f;
#pragma unroll
            for (int t = LQ - 1; t >= 0; t--) {
                qv = fmaf(p, Qe[(b * LQ + t) * EE + d], qv);
                p *= ALPHA;
            }
            dot = fmaf(qv, wrow[d], dot);
        }
#pragma unroll
        for (int o = 16; o > 0; o >>= 1) dot += __shfl_xor_sync(0xffffffffu, dot, o);
        if (lane == 0) g_Pq[b * H1 + j] = b1[j] - m1[j] * sc + sc * dot;
        return;
    }
    bx -= PREP_PQ;
    {
        const long total = H2 + T_LEN + MSPAN + (CLEN + 1) + (long)ROWS * 2;
        for (long idx = (long)bx * 256 + tid; idx < total; idx += (long)PREP_MISC * 256) {
            long i = idx;
            if (i < H2) {
                float sc = g2[i] * rsqrtf(v2[i] + EPS);
                g_sh2[i] = b2[i] - m2[i] * sc;
                continue;
            }
            i -= H2;
            if (i < T_LEN) {
                int s = (int)i;
                int cnt = min(MSPAN, T_LEN - s);
                int ex = (s > 794) ? ((s - 794) * (s - 793)) / 2 : 0;
                int base = 16 * s - ex;
                for (int sp = 0; sp < cnt; sp++) {
                    g_sidx[base + sp] = s;
                    g_eidx[base + sp] = s + sp;
                }
                continue;
            }
            i -= T_LEN;
            if (i < MSPAN) {
                double c = 1.0;
                for (int k = 0; k <= (int)i; k++) c *= 0.9;
                g_coef[i] = (float)c;
                continue;
            }
            i -= MSPAN;
            if (i < CLEN + 1) {
                double c = 1.0;
                for (int k = 0; k < (int)i; k++) c *= 0.9;
                g_apow[i] = (float)c;
                continue;
            }
            i -= (CLEN + 1);
            out[i] = 0.f;
        }
    }
}

// ------- scan carries -------
__global__ void k_scan2() {
    const int d = threadIdx.x;
    const int b = blockIdx.x;
    const size_t base = (size_t)b * TPAD * DD;
    if (blockIdx.y == 0) {
        float carry = 0.f;
        const float a64 = g_apow[CLEN];
#pragma unroll 1
        for (int c = 0; c < NCHUNK; c++) {
            g_carryF[(b * NCHUNK + c) * DD + d] = carry;
            if (c < NCHUNK - 1) {
                float E = g_Ltmp[base + (size_t)((c + 1) * CLEN) * DD + d];
                carry = fmaf(a64, carry, E);
            }
        }
    } else {
        float carry = 0.f;
#pragma unroll 1
        for (int c = NCHUNK - 1; c >= 0; c--) {
            g_carryR[(b * NCHUNK + c) * DD + d] = carry;
            if (c > 0) {
                int len = min(CLEN, T_LEN - c * CLEN);
                float M = g_Mtmp[base + (size_t)(c * CLEN) * DD + d];
                carry = fmaf(g_apow[len], carry, M);
            }
        }
    }
}

// ------- apply carries + fp16 hi/lo split -------
constexpr int SC3_Q = DD / 4;
__global__ void __launch_bounds__(256) k_scan3() {
    int idx = blockIdx.x * 256 + threadIdx.x;
    const int total = 2 * BB * TPAD * SC3_Q;
    if (idx >= total) return;
    const int q = idx % SC3_Q;
    int rem = idx / SC3_Q;
    const int r = rem % TPAD;
    rem /= TPAD;
    const int b = rem % BB;
    const int dir = rem / BB;
    const int d = q * 4;
    const size_t ro = ((size_t)b * TPAD + r) * DD + d;

    float v[4];
    if (dir == 0) {
        __half zero = __float2half_rn(0.f);
        if (r == 0) {
            ((__half2*)&g_Fph[ro])[0] = __half2half2(zero);
            ((__half2*)&g_Fph[ro])[1] = __half2half2(zero);
            ((__half2*)&g_Fpl[ro])[0] = __half2half2(zero);
            ((__half2*)&g_Fpl[ro])[1] = __half2half2(zero);
            return;
        }
        int t = r - 1;
        int chunk = t >> 6;
        float p = g_apow[(t & 63) + 1];
        float4 L = *(const float4*)&g_Ltmp[ro];
        float4 C = *(const float4*)&g_carryF[(b * NCHUNK + chunk) * DD + d];
        v[0] = fmaf(p, C.x, L.x); v[1] = fmaf(p, C.y, L.y);
        v[2] = fmaf(p, C.z, L.z); v[3] = fmaf(p, C.w, L.w);
        __half2 h0 = __floats2half2_rn(v[0], v[1]);
        __half2 h1 = __floats2half2_rn(v[2], v[3]);
        float2 f0 = __half22float2(h0), f1 = __half22float2(h1);
        ((__half2*)&g_Fph[ro])[0] = h0;
        ((__half2*)&g_Fph[ro])[1] = h1;
        ((__half2*)&g_Fpl[ro])[0] = __floats2half2_rn(v[0] - f0.x, v[1] - f0.y);
        ((__half2*)&g_Fpl[ro])[1] = __floats2half2_rn(v[2] - f1.x, v[3] - f1.y);
    } else {
        __half zero = __float2half_rn(0.f);
        if (r == T_LEN) {
            ((__half2*)&g_Rph[ro])[0] = __half2half2(zero);
            ((__half2*)&g_Rph[ro])[1] = __half2half2(zero);
            ((__half2*)&g_Rpl[ro])[0] = __half2half2(zero);
            ((__half2*)&g_Rpl[ro])[1] = __half2half2(zero);
            return;
        }
        int t = r;
        int chunk = t >> 6;
        int end = min(T_LEN, (chunk + 1) << 6);
        float p = g_apow[end - t];
        float4 M = *(const float4*)&g_Mtmp[ro];
        float4 C = *(const float4*)&g_carryR[(b * NCHUNK + chunk) * DD + d];
        v[0] = fmaf(p, C.x, M.x); v[1] = fmaf(p, C.y, M.y);
        v[2] = fmaf(p, C.z, M.z); v[3] = fmaf(p, C.w, M.w);
        __half2 h0 = __floats2half2_rn(v[0], v[1]);
        __half2 h1 = __floats2half2_rn(v[2], v[3]);
        float2 f0 = __half22float2(h0), f1 = __half22float2(h1);
        ((__half2*)&g_Rph[ro])[0] = h0;
        ((__half2*)&g_Rph[ro])[1] = h1;
        ((__half2*)&g_Rpl[ro])[0] = __floats2half2_rn(v[0] - f0.x, v[1] - f0.y);
        ((__half2*)&g_Rpl[ro])[1] = __floats2half2_rn(v[2] - f1.x, v[3] - f1.y);
    }
}

// ---------- projections: fp16 mma, single sync/chunk; z<2 K=32, z=2 K=16 ----
constexpr int PJ_SB = 272;
// z<2 (K=32) stage layout
constexpr uint32_t P2_AH = 0;        // 128*80 = 10240
constexpr uint32_t P2_AL = 10240;
constexpr uint32_t P2_B  = 20480;    // 32*272 = 8704  -> 29184 used
// z=2 (K=16) stage layout
constexpr int PJ_SA = 48;
constexpr uint32_t PJ_AHF = 0;
constexpr uint32_t PJ_ALF = 6144;
constexpr uint32_t PJ_AHR = 12288;
constexpr uint32_t PJ_ALR = 18432;
constexpr uint32_t PJ_BB  = 24576;
constexpr uint32_t PJ_BC  = 28928;
constexpr uint32_t PJ_STAGE = 33280;
constexpr uint32_t PJ_SMEM = 2 * PJ_STAGE;   // 66560

__global__ void __launch_bounds__(256) k_proj() {
    extern __shared__ char sm[];
    const uint32_t sb = smem_u32(sm);
    const int z = blockIdx.z;
    const int m0 = blockIdx.x * 128;
    const int n0 = blockIdx.y * 128;
    const int tid = threadIdx.x;
    const int lane = tid & 31;
    const int w = tid >> 5;
    const int mw = w & 3;
    const int nw = w >> 2;

    __half* P = (z == 0) ? g_PX : (z == 1 ? g_PY : g_PE);

    const int amm = tid >> 1, aseg = tid & 1;
    const int am = (m0 + amm < MROWS) ? (m0 + amm) : 0;
    const int bkr = tid >> 4, bns = tid & 15;

    float acc[2][8][4];
#pragma unroll
    for (int i = 0; i < 2; i++)
#pragma unroll
        for (int j = 0; j < 8; j++)
#pragma unroll
            for (int c = 0; c < 4; c++) acc[i][j][c] = 0.f;

    const uint32_t bRel = (uint32_t)((lane & 15) * PJ_SB + (nw * 64 + (lane >> 4) * 8) * 2);

    if (z < 2) {
        // ---- K=32 path, 10 chunks (pad zeros beyond 304) ----
        const uint32_t aRel32 = (uint32_t)((mw * 32 + (lane & 15)) * 80 + (lane >> 4) * 16);
        auto stage32 = [&](int cc) {
            const uint32_t st = sb + (uint32_t)(cc & 1) * PJ_STAGE;
            const int k0 = cc * 32;
            const size_t asrc = (size_t)am * DD + k0 + aseg * 16;
            const uint32_t adst = (uint32_t)(amm * 80 + aseg * 32);
            cp16(st + P2_AH + adst,      g_Fph + asrc);
            cp16(st + P2_AH + adst + 16, g_Fph + asrc + 8);
            cp16(st + P2_AL + adst,      g_Fpl + asrc);
            cp16(st + P2_AL + adst + 16, g_Fpl + asrc + 8);
#pragma unroll
            for (int h = 0; h < 2; h++) {
                int kr = bkr + h * 16;
                const size_t bsrc = ((size_t)(z * KPAD + k0 + kr)) * H1 + n0 + bns * 8;
                cp16(st + P2_B + (uint32_t)(kr * PJ_SB + bns * 16), g_W1h3 + bsrc);
            }
            cp_commit();
        };
        stage32(0);
        cp_wait<0>();
        __syncthreads();
#pragma unroll 1
        for (int c = 0; c < 10; c++) {
            if (c < 9) stage32(c + 1);
            const uint32_t st = sb + (uint32_t)(c & 1) * PJ_STAGE;
#pragma unroll
            for (int s = 0; s < 2; s++) {
                uint32_t ah[2][4], al[2][4];
                ldsm_x4(ah[0], st + P2_AH + aRel32 + s * 32);
                ldsm_x4(ah[1], st + P2_AH + aRel32 + s * 32 + 16 * 80);
                ldsm_x4(al[0], st + P2_AL + aRel32 + s * 32);
                ldsm_x4(al[1], st + P2_AL + aRel32 + s * 32 + 16 * 80);
                const uint32_t kbq = st + P2_B + bRel + (uint32_t)(s * 16 * PJ_SB);
#pragma unroll
                for (int g = 0; g < 4; g++) {
                    uint32_t bh[4];
                    ldsm_x4_t(bh, kbq + g * 32);
#pragma unroll
                    for (int m = 0; m < 2; m++) {
                        mma16816(acc[m][2 * g],     ah[m], bh);
                        mma16816(acc[m][2 * g + 1], ah[m], bh + 2);
                        mma16816(acc[m][2 * g],     al[m], bh);
                        mma16816(acc[m][2 * g + 1], al[m], bh + 2);
                    }
                }
            }
            if (c < 9) { cp_wait<0>(); __syncthreads(); }
        }
    } else {
        // ---- z=2: K=16, 19 chunks, dual accumulation (Fp@W1b + Rp@W1c) ----
        const uint32_t aRel = (uint32_t)((mw * 32 + (lane & 15)) * PJ_SA + (lane >> 4) * 16);
        auto stage = [&](int cc) {
            const uint32_t st = sb + (uint32_t)(cc & 1) * PJ_STAGE;
            const int k0 = cc * 16;
            const size_t asrc = ((size_t)am * DD + k0 + aseg * 8);
            const uint32_t adst = (uint32_t)(amm * PJ_SA + aseg * 16);
            cp16(st + PJ_AHF + adst, g_Fph + asrc);
            cp16(st + PJ_ALF + adst, g_Fpl + asrc);
            cp16(st + PJ_AHR + adst, g_Rph + asrc);
            cp16(st + PJ_ALR + adst, g_Rpl + asrc);
            const size_t bsb = ((size_t)(1 * KPAD + k0 + bkr)) * H1 + n0 + bns * 8;
            const size_t bsc = ((size_t)(2 * KPAD + k0 + bkr)) * H1 + n0 + bns * 8;
            cp16(st + PJ_BB + (uint32_t)(bkr * PJ_SB + bns * 16), g_W1h3 + bsb);
            cp16(st + PJ_BC + (uint32_t)(bkr * PJ_SB + bns * 16), g_W1h3 + bsc);
            cp_commit();
        };
        stage(0);
        cp_wait<0>();
        __syncthreads();
#pragma unroll 1
        for (int c = 0; c < 19; c++) {
            if (c < 18) stage(c + 1);
            const uint32_t st = sb + (uint32_t)(c & 1) * PJ_STAGE;
            uint32_t ah[2][4], al[2][4];
            ldsm_x4(ah[0], st + PJ_AHF + aRel);
            ldsm_x4(ah[1], st + PJ_AHF + aRel + 16 * PJ_SA);
            ldsm_x4(al[0], st + PJ_ALF + aRel);
            ldsm_x4(al[1], st + PJ_ALF + aRel + 16 * PJ_SA);
#pragma unroll
            for (int g = 0; g < 4; g++) {
                uint32_t bh[4];
                ldsm_x4_t(bh, st + PJ_BB + bRel + g * 32);
#pragma unroll
                for (int m = 0; m < 2; m++) {
                    mma16816(acc[m][2 * g],     ah[m], bh);
                    mma16816(acc[m][2 * g + 1], ah[m], bh + 2);
                    mma16816(acc[m][2 * g],     al[m], bh);
                    mma16816(acc[m][2 * g + 1], al[m], bh + 2);
                }
            }
            uint32_t ahr[2][4], alr[2][4];
            ldsm_x4(ahr[0], st + PJ_AHR + aRel);
            ldsm_x4(ahr[1], st + PJ_AHR + aRel + 16 * PJ_SA);
            ldsm_x4(alr[0], st + PJ_ALR + aRel);
            ldsm_x4(alr[1], st + PJ_ALR + aRel + 16 * PJ_SA);
#pragma unroll
            for (int g = 0; g < 4; g++) {
                uint32_t bh[4];
                ldsm_x4_t(bh, st + PJ_BC + bRel + g * 32);
#pragma unroll
                for (int m = 0; m < 2; m++) {
                    mma16816(acc[m][2 * g],     ahr[m], bh);
                    mma16816(acc[m][2 * g + 1], ahr[m], bh + 2);
                    mma16816(acc[m][2 * g],     alr[m], bh);
                    mma16816(acc[m][2 * g + 1], alr[m], bh + 2);
                }
            }
            if (c < 18) { cp_wait<0>(); __syncthreads(); }
        }
    }

#pragma unroll
    for (int m = 0; m < 2; m++) {
        int row0 = m0 + mw * 32 + m * 16 + (lane >> 2);
#pragma unroll
        for (int h = 0; h < 2; h++) {
            int row = row0 + h * 8;
            if (row >= MROWS) continue;
            const int col = n0 + nw * 64 + (lane & 3) * 2;
            __half2* pr = (__half2*)&P[(size_t)row * H1 + col];
            const float* qr = (z == 0) ? &g_Pq[(row / TPAD) * H1 + col] : nullptr;
#pragma unroll
            for (int nf = 0; nf < 8; nf++) {
                float vx = acc[m][nf][2 * h];
                float vy = acc[m][nf][2 * h + 1];
                if (z == 0) {
                    vx += qr[nf * 8];
                    vy += qr[nf * 8 + 1];
                }
                pr[nf * 4] = __floats2half2_rn(vx, vy);
            }
        }
    }
}

// ---- main: fp16 mma GEMM2, register-pipelined A-gen (R13 structure) ----
constexpr int SA_STRIDE = 144;
constexpr int SB_STRIDE = 528;
constexpr uint32_t OFF_AH   = 0;
constexpr uint32_t OFF_BH   = 9216;
constexpr uint32_t STAGE_SZ = 43008;
constexpr uint32_t OFF_HDR  = 86016;
constexpr uint32_t OFF_OS   = OFF_HDR;
constexpr uint32_t OFF_OE   = OFF_HDR + 256;
constexpr uint32_t OFF_CF   = OFF_HDR + 512;
constexpr uint32_t OFF_W3A  = OFF_HDR + 768;
constexpr uint32_t OFF_W3B  = OFF_HDR + 1792;
constexpr uint32_t OFF_SH2  = OFF_HDR + 2816;
constexpr uint32_t OFF_RED  = OFF_HDR + 3840;
constexpr uint32_t SMEM_MAIN = OFF_HDR + 5888;

__global__ void __launch_bounds__(256, 2) k_main(const float* __restrict__ W3,
                                                 float* __restrict__ out) {
    extern __shared__ char sm[];
    const uint32_t sb = smem_u32(sm);
    const int tid = threadIdx.x;
    const int lane = tid & 31;
    const int w = tid >> 5;
    const int mw = w & 1;
    const int nw = w >> 1;
    const int batch = blockIdx.y;
    const int c0i = blockIdx.x * 64;
    const int n0 = blockIdx.z * 256;

    int*   sOS = (int*)(sm + OFF_OS);
    int*   sOE = (int*)(sm + OFF_OE);
    float* sCF = (float*)(sm + OFF_CF);
    float* sW3a = (float*)(sm + OFF_W3A);
    float* sW3b = (float*)(sm + OFF_W3B);
    float* sSh2 = (float*)(sm + OFF_SH2);
    float* sRed = (float*)(sm + OFF_RED);

    if (tid < 64) {
        int ci = c0i + tid;
        int offS = 0, offE = 0;
        float cf = 0.f;
        if (ci < NCAND) {
            int s = g_sidx[ci], e = g_eidx[ci];
            offS = (batch * TPAD + s) * H1;
            offE = (batch * TPAD + e + 1) * H1;
            cf = g_coef[e - s];
        }
        sOS[tid] = offS; sOE[tid] = offE; sCF[tid] = cf;
    }
    sW3a[tid] = W3[n0 + tid];
    sW3b[tid] = W3[H2 + n0 + tid];
    sSh2[tid] = g_sh2[n0 + tid];
    __syncthreads();

    const int wrow = w * 8;
    const int myOS = sOS[wrow + (lane & 7)];
    const int myOE = sOE[wrow + (lane & 7)];
    const float myCF = sCF[wrow + (lane & 7)];
    const bool uni = (__shfl_sync(0xffffffffu, myOS, 0) ==
                      __shfl_sync(0xffffffffu, myOS, 7));
    const int offSu = __shfl_sync(0xffffffffu, myOS, 0);
    int offEr[8];
    float cfr[8];
#pragma unroll
    for (int rr = 0; rr < 8; rr++) {
        offEr[rr] = __shfl_sync(0xffffffffu, myOE, rr);
        cfr[rr] = __shfl_sync(0xffffffffu, myCF, rr);
    }
    int offSr[8];
#pragma unroll
    for (int rr = 0; rr < 8; rr++) offSr[rr] = __shfl_sync(0xffffffffu, myOS, rr);

    const int bkr = tid >> 5;
    const int bnc = tid & 31;

    const uint32_t aRel = OFF_AH + (uint32_t)((mw * 32 + (lane & 15)) * SA_STRIDE +
                                              ((lane >> 4) * 8) * 2);
    const uint32_t bRel = OFF_BH + (uint32_t)((lane & 15) * SB_STRIDE +
                                              (nw * 64 + (lane >> 4) * 8) * 2);

    float acc[2][8][4];
#pragma unroll
    for (int t = 0; t < 2; t++)
#pragma unroll
        for (int nf = 0; nf < 8; nf++)
#pragma unroll
            for (int c = 0; c < 4; c++) acc[t][nf][c] = 0.f;

    auto issueB = [&](int cc) {
        const uint32_t st = sb + (uint32_t)(cc & 1) * STAGE_SZ;
        const __half* bsrc = &g_W2h16[(size_t)(cc * 64) * H2 + n0];
#pragma unroll
        for (int it = 0; it < 8; it++) {
            int kr = bkr + it * 8;
            cp16(st + OFF_BH + (uint32_t)(kr * SB_STRIDE + bnc * 16),
                 bsrc + (size_t)kr * H2 + bnc * 8);
        }
        cp_commit();
    };

    __half2 er[8], xr[8], yr[8];
    auto ldA = [&](int cc) {
        const int kc = cc * 64 + 2 * lane;
#pragma unroll
        for (int rr = 0; rr < 8; rr++)
            er[rr] = *(const __half2*)&g_PE[offEr[rr] + kc];
        if (uni) {
            xr[0] = *(const __half2*)&g_PX[offSu + kc];
            yr[0] = *(const __half2*)&g_PY[offSu + kc];
        } else {
#pragma unroll
            for (int rr = 0; rr < 8; rr++) {
                xr[rr] = *(const __half2*)&g_PX[offSr[rr] + kc];
                yr[rr] = *(const __half2*)&g_PY[offSr[rr] + kc];
            }
        }
    };
    auto cvtStore = [&](int cc) {
        const uint32_t stoff = (uint32_t)(cc & 1) * STAGE_SZ;
        if (uni) {
            float2 x = __half22float2(xr[0]);
            float2 y = __half22float2(yr[0]);
#pragma unroll
            for (int rr = 0; rr < 8; rr++) {
                float2 e = __half22float2(er[rr]);
                float v0 = fmaxf(x.x + e.x - cfr[rr] * y.x, 0.f);
                float v1 = fmaxf(x.y + e.y - cfr[rr] * y.y, 0.f);
                __half2 h = __floats2half2_rn(v0, v1);
                uint32_t ad = stoff + (uint32_t)((wrow + rr) * SA_STRIDE + lane * 4);
                *(uint32_t*)(sm + OFF_AH + ad) = h2u(h);
            }
        } else {
#pragma unroll
            for (int rr = 0; rr < 8; rr++) {
                float2 x = __half22float2(xr[rr]);
                float2 y = __half22float2(yr[rr]);
                float2 e = __half22float2(er[rr]);
                float v0 = fmaxf(x.x + e.x - cfr[rr] * y.x, 0.f);
                float v1 = fmaxf(x.y + e.y - cfr[rr] * y.y, 0.f);
                __half2 h = __floats2half2_rn(v0, v1);
                uint32_t ad = stoff + (uint32_t)((wrow + rr) * SA_STRIDE + lane * 4);
                *(uint32_t*)(sm + OFF_AH + ad) = h2u(h);
            }
        }
    };

    issueB(0);
    ldA(0);
    cvtStore(0);
    cp_wait<0>();
    __syncthreads();

#pragma unroll 1
    for (int c = 0; c < 16; c++) {
        if (c < 15) {
            issueB(c + 1);
            ldA(c + 1);
        }
        const uint32_t st = sb + (uint32_t)(c & 1) * STAGE_SZ;
#pragma unroll
        for (int s = 0; s < 4; s++) {
            const uint32_t ka = st + aRel + (uint32_t)(s * 32);
            uint32_t ah[2][4];
            ldsm_x4(ah[0], ka);
            ldsm_x4(ah[1], ka + 16 * SA_STRIDE);
            const uint32_t kbq = st + bRel + (uint32_t)(s * 16 * SB_STRIDE);
#pragma unroll
            for (int p = 0; p < 4; p++) {
                uint32_t bq[4];
                ldsm_x4_t(bq, kbq + p * 32);
                mma16816(acc[0][2 * p],     ah[0], bq);
                mma16816(acc[1][2 * p],     ah[1], bq);
                mma16816(acc[0][2 * p + 1], ah[0], bq + 2);
                mma16816(acc[1][2 * p + 1], ah[1], bq + 2);
            }
        }
        if (c < 15) {
            cvtStore(c + 1);
            cp_wait<0>();
            __syncthreads();
        }
    }

    // ---- epilogue: relu(D + sh2) dot W3, reduce, atomicAdd ----
    float sums[4][2];
#pragma unroll
    for (int q = 0; q < 4; q++) { sums[q][0] = 0.f; sums[q][1] = 0.f; }
#pragma unroll
    for (int t = 0; t < 2; t++) {
#pragma unroll
        for (int nf = 0; nf < 8; nf++) {
            int n = nw * 64 + nf * 8 + (lane & 3) * 2;
            float sh0 = sSh2[n], sh1 = sSh2[n + 1];
            float wa0 = sW3a[n], wa1 = sW3a[n + 1];
            float wb0 = sW3b[n], wb1 = sW3b[n + 1];
            float v0 = fmaxf(acc[t][nf][0] + sh0, 0.f);
            float v1 = fmaxf(acc[t][nf][1] + sh1, 0.f);
            float v2 = fmaxf(acc[t][nf][2] + sh0, 0.f);
            float v3 = fmaxf(acc[t][nf][3] + sh1, 0.f);
            sums[t * 2][0]     = fmaf(v0, wa0, fmaf(v1, wa1, sums[t * 2][0]));
            sums[t * 2][1]     = fmaf(v0, wb0, fmaf(v1, wb1, sums[t * 2][1]));
            sums[t * 2 + 1][0] = fmaf(v2, wa0, fmaf(v3, wa1, sums[t * 2 + 1][0]));
            sums[t * 2 + 1][1] = fmaf(v2, wb0, fmaf(v3, wb1, sums[t * 2 + 1][1]));
        }
    }
#pragma unroll
    for (int q = 0; q < 4; q++) {
#pragma unroll
        for (int o = 0; o < 2; o++) {
            sums[q][o] += __shfl_xor_sync(0xffffffffu, sums[q][o], 1);
            sums[q][o] += __shfl_xor_sync(0xffffffffu, sums[q][o], 2);
        }
    }
    __syncthreads();
    if ((lane & 3) == 0) {
#pragma unroll
        for (int q = 0; q < 4; q++) {
            int rloc = mw * 32 + (q >> 1) * 16 + (q & 1) * 8 + (lane >> 2);
            sRed[nw * 128 + rloc * 2 + 0] = sums[q][0];
            sRed[nw * 128 + rloc * 2 + 1] = sums[q][1];
        }
    }
    __syncthreads();
    if (tid < 128) {
        int rloc = tid >> 1, o = tid & 1;
        int ci = c0i + rloc;
        if (ci < NCAND) {
            float v = sRed[rloc * 2 + o] + sRed[128 + rloc * 2 + o] +
                      sRed[256 + rloc * 2 + o] + sRed[384 + rloc * 2 + o];
            atomicAdd(&out[(size_t)(batch * NCAND + ci) * 2 + o], v);
        }
    }
}

// ---------------- launch ----------------
extern "C" void kernel_launch(void* const* d_in, const int* in_sizes, int n_in,
                              void* d_out, int out_size) {
    (void)in_sizes; (void)n_in; (void)out_size;
    const float* doc = (const float*)d_in[0];
    const float* qe  = (const float*)d_in[1];
    const float* W1  = (const float*)d_in[2];
    const float* g1  = (const float*)d_in[3];
    const float* b1  = (const float*)d_in[4];
    const float* m1  = (const float*)d_in[5];
    const float* v1  = (const float*)d_in[6];
    const float* W2  = (const float*)d_in[7];
    const float* g2  = (const float*)d_in[8];
    const float* b2  = (const float*)d_in[9];
    const float* m2  = (const float*)d_in[10];
    const float* v2  = (const float*)d_in[11];
    const float* W3  = (const float*)d_in[12];
    float* out = (float*)d_out;

    cudaFuncSetAttribute(k_main, cudaFuncAttributeMaxDynamicSharedMemorySize, SMEM_MAIN);
    cudaFuncSetAttribute(k_proj, cudaFuncAttributeMaxDynamicSharedMemorySize, PJ_SMEM);

    k_prep<<<PREP_GRID, 256>>>(doc, qe, W1, g1, b1, m1, v1, W2, g2, b2, m2, v2, out);
    k_scan2<<<dim3(BB, 2), DD>>>();
    k_scan3<<<(2 * BB * TPAD * SC3_Q + 255) / 256, 256>>>();
    k_proj<<<dim3((MROWS + 127) / 128, H1 / 128, 3), 256, PJ_SMEM>>>();
    k_main<<<dim3((NCAND + 63) / 64, BB, 2), 256, SMEM_MAIN>>>(W3, out);
}

// round 15
// speedup vs baseline: 1.4056x; 1.0504x over previous
#include <cuda_runtime.h>
#include <cuda_fp16.h>
#include <cstdint>

#define ALPHA 0.9f
constexpr int T_LEN = 809;
constexpr int TPAD  = 810;
constexpr int DD    = 304;
constexpr int EE    = 300;
constexpr int LQ    = 30;
constexpr int BB    = 4;
constexpr int MSPAN = 16;
constexpr int H1    = 1024;
constexpr int H2    = 512;
constexpr int CIN   = 1212;
constexpr int NCAND = 12824;
constexpr int ROWS  = BB * NCAND;      // 51296
constexpr int MROWS = BB * TPAD;       // 3240
constexpr float EPS = 1e-5f;
constexpr int CLEN   = 64;
constexpr int NCHUNK = 13;
constexpr int KPAD   = 320;

// ---------------- scratch ----------------
__device__ __align__(16) __half g_Fph[MROWS * DD + 16];   // +16 zeroed tail
__device__ __align__(16) __half g_Fpl[MROWS * DD + 16];
__device__ __align__(16) __half g_Rph[MROWS * DD + 16];
__device__ __align__(16) __half g_Rpl[MROWS * DD + 16];
__device__ __align__(16) float g_Ltmp[MROWS * DD];
__device__ __align__(16) float g_Mtmp[MROWS * DD];
__device__ float g_carryF[BB * NCHUNK * DD];
__device__ float g_carryR[BB * NCHUNK * DD];
__device__ float g_apow[CLEN + 1];
__device__ __align__(16) __half g_W1h3[3 * KPAD * H1];    // [z][kpad][n], pad rows zero
__device__ __align__(16) __half g_PX[MROWS * H1];         // fp16(PA + Pq)
__device__ __align__(16) __half g_PY[MROWS * H1];         // fp16(PB)
__device__ __align__(16) __half g_PE[MROWS * H1];         // PC, then += PY -> PE
__device__ float g_Pq[BB * H1];
__device__ __align__(16) __half g_W2h16[H1 * H2];
__device__ float g_sh2[H2];
__device__ float g_coef[MSPAN];
__device__ int   g_sidx[NCAND];
__device__ int   g_eidx[NCAND];

// ---------------- helpers ----------------
__device__ __forceinline__ uint32_t smem_u32(const void* p) {
    uint32_t a;
    asm("{ .reg .u64 t; cvta.to.shared.u64 t, %1; cvt.u32.u64 %0, t; }" : "=r"(a) : "l"(p));
    return a;
}
__device__ __forceinline__ uint32_t h2u(__half2 h) { return *(uint32_t*)&h; }

__device__ __forceinline__ void ldsm_x4(uint32_t* r, uint32_t a) {
    asm volatile("ldmatrix.sync.aligned.m8n8.x4.shared.b16 {%0,%1,%2,%3}, [%4];"
                 : "=r"(r[0]), "=r"(r[1]), "=r"(r[2]), "=r"(r[3]) : "r"(a));
}
__device__ __forceinline__ void ldsm_x4_t(uint32_t* r, uint32_t a) {
    asm volatile("ldmatrix.sync.aligned.m8n8.x4.trans.shared.b16 {%0,%1,%2,%3}, [%4];"
                 : "=r"(r[0]), "=r"(r[1]), "=r"(r[2]), "=r"(r[3]) : "r"(a));
}
__device__ __forceinline__ void mma16816(float* d, const uint32_t* a, const uint32_t* b) {
    asm volatile(
        "mma.sync.aligned.m16n8k16.row.col.f32.f16.f16.f32 "
        "{%0,%1,%2,%3}, {%4,%5,%6,%7}, {%8,%9}, {%0,%1,%2,%3};"
        : "+f"(d[0]), "+f"(d[1]), "+f"(d[2]), "+f"(d[3])
        : "r"(a[0]), "r"(a[1]), "r"(a[2]), "r"(a[3]), "r"(b[0]), "r"(b[1]));
}
__device__ __forceinline__ void cp16(uint32_t dst, const void* src) {
    asm volatile("cp.async.cg.shared.global [%0], [%1], 16;" :: "r"(dst), "l"(src));
}
__device__ __forceinline__ void cp_commit() { asm volatile("cp.async.commit_group;"); }
template <int N> __device__ __forceinline__ void cp_wait() {
    asm volatile("cp.async.wait_group %0;" :: "n"(N));
}

// =================== fat prep kernel ==============
constexpr int PREP_W2   = 512;
constexpr int PREP_W1   = 960;
constexpr int PREP_SC1  = BB * 2 * NCHUNK;
constexpr int PREP_PQ   = 512;
constexpr int PREP_MISC = 64;
constexpr int PREP_GRID = PREP_W2 + PREP_W1 + PREP_SC1 + PREP_PQ + PREP_MISC;

__global__ void __launch_bounds__(256) k_prep(
    const float* __restrict__ doc, const float* __restrict__ Qe,
    const float* __restrict__ W1,
    const float* __restrict__ g1, const float* __restrict__ b1,
    const float* __restrict__ m1, const float* __restrict__ v1,
    const float* __restrict__ W2,
    const float* __restrict__ g2, const float* __restrict__ b2,
    const float* __restrict__ m2, const float* __restrict__ v2,
    float* __restrict__ out) {
    __shared__ float sh[32 * DD];
    int bx = blockIdx.x;
    const int tid = threadIdx.x;

    if (bx < PREP_W2) {
        float (*tl)[33] = (float(*)[33])sh;
        const int kt = bx & 31, nt = bx >> 5;
        const int k0 = kt * 32, n0 = nt * 32;
        const int tx = tid & 31, ty = tid >> 5;
#pragma unroll
        for (int it = 0; it < 4; it++)
            tl[ty + it * 8][tx] = W2[(size_t)(n0 + ty + it * 8) * H1 + k0 + tx];
        __syncthreads();
        const int n = n0 + tx;
        const float sc = g2[n] * rsqrtf(v2[n] + EPS);
#pragma unroll
        for (int it = 0; it < 4; it++) {
            int k = k0 + ty + it * 8;
            g_W2h16[(size_t)k * H2 + n] = __float2half_rn(tl[tx][ty + it * 8] * sc);
        }
        return;
    }
    bx -= PREP_W2;
    if (bx < PREP_W1) {
        float (*tl)[33] = (float(*)[33])sh;
        const int z = bx / 320;
        const int r = bx - z * 320;
        const int kt = r % 10, nt = r / 10;
        const int k0 = kt * 32, n0 = nt * 32;
        const int tx = tid & 31, ty = tid >> 5;
#pragma unroll
        for (int it = 0; it < 4; it++) {
            int n = n0 + ty + it * 8;
            int k = k0 + tx;
            tl[ty + it * 8][tx] = (k < DD) ? W1[(size_t)n * CIN + z * DD + k] : 0.f;
        }
        __syncthreads();
        const int n = n0 + tx;
        const float sc = g1[n] * rsqrtf(v1[n] + EPS);
#pragma unroll
        for (int it = 0; it < 4; it++) {
            int k = k0 + ty + it * 8;
            g_W1h3[((size_t)(z * KPAD + k)) * H1 + n] =
                __float2half_rn(tl[tx][ty + it * 8] * sc);
        }
        return;
    }
    bx -= PREP_W1;
    if (bx < PREP_SC1) {
        const int dir = bx & 1;
        const int rest = bx >> 1;
        const int b = rest / NCHUNK;
        const int chunk = rest - b * NCHUNK;
        const int tstart = chunk * CLEN;
        const int tend = min(T_LEN, tstart + CLEN);
        const float* dp = doc + (size_t)b * T_LEN * DD;
        const int d0 = tid, d1 = tid + 256;
        const bool has1 = (d1 < DD);
        const size_t base = (size_t)b * TPAD * DD;
        if (dir == 0) {
            float a0 = 0.f, a1 = 0.f;
            for (int t0 = tstart; t0 < tend; t0 += 32) {
                int n = min(32, tend - t0);
                __syncthreads();
                for (int i = tid; i < n * DD; i += 256) sh[i] = dp[(size_t)t0 * DD + i];
                __syncthreads();
                for (int i = 0; i < n; i++) {
                    size_t ro = base + (size_t)(t0 + i + 1) * DD;
                    a0 = fmaf(ALPHA, a0, sh[i * DD + d0]);
                    g_Ltmp[ro + d0] = a0;
                    if (has1) {
                        a1 = fmaf(ALPHA, a1, sh[i * DD + d1]);
                        g_Ltmp[ro + d1] = a1;
                    }
                }
            }
        } else {
            float a0 = 0.f, a1 = 0.f;
            for (int hi = tend; hi > tstart; hi -= 32) {
                int lo = max(tstart, hi - 32);
                int n = hi - lo;
                __syncthreads();
                for (int i = tid; i < n * DD; i += 256) sh[i] = dp[(size_t)lo * DD + i];
                __syncthreads();
                for (int i = n - 1; i >= 0; i--) {
                    size_t ro = base + (size_t)(lo + i) * DD;
                    a0 = fmaf(ALPHA, a0, sh[i * DD + d0]);
                    g_Mtmp[ro + d0] = a0;
                    if (has1) {
                        a1 = fmaf(ALPHA, a1, sh[i * DD + d1]);
                        g_Mtmp[ro + d1] = a1;
                    }
                }
            }
        }
        return;
    }
    bx -= PREP_SC1;
    if (bx < PREP_PQ) {
        const int lane = tid & 31;
        const int gw = bx * 8 + (tid >> 5);
        const int j = gw & (H1 - 1);
        const int b = gw >> 10;
        const float sc = g1[j] * rsqrtf(v1[j] + EPS);
        const float* wrow = &W1[(size_t)j * CIN + 3 * DD];
        float dot = 0.f;
        for (int d = lane; d < EE; d += 32) {
            float qv = 0.f, p = 1.f;
#pragma unroll
            for (int t = LQ - 1; t >= 0; t--) {
                qv = fmaf(p, Qe[(b * LQ + t) * EE + d], qv);
                p *= ALPHA;
            }
            dot = fmaf(qv, wrow[d], dot);
        }
#pragma unroll
        for (int o = 16; o > 0; o >>= 1) dot += __shfl_xor_sync(0xffffffffu, dot, o);
        if (lane == 0) g_Pq[b * H1 + j] = b1[j] - m1[j] * sc + sc * dot;
        return;
    }
    bx -= PREP_PQ;
    {
        const long total = H2 + T_LEN + MSPAN + (CLEN + 1) + 64 + (long)ROWS * 2;
        for (long idx = (long)bx * 256 + tid; idx < total; idx += (long)PREP_MISC * 256) {
            long i = idx;
            if (i < H2) {
                float sc = g2[i] * rsqrtf(v2[i] + EPS);
                g_sh2[i] = b2[i] - m2[i] * sc;
                continue;
            }
            i -= H2;
            if (i < T_LEN) {
                int s = (int)i;
                int cnt = min(MSPAN, T_LEN - s);
                int ex = (s > 794) ? ((s - 794) * (s - 793)) / 2 : 0;
                int base = 16 * s - ex;
                for (int sp = 0; sp < cnt; sp++) {
                    g_sidx[base + sp] = s;
                    g_eidx[base + sp] = s + sp;
                }
                continue;
            }
            i -= T_LEN;
            if (i < MSPAN) {
                double c = 1.0;
                for (int k = 0; k <= (int)i; k++) c *= 0.9;
                g_coef[i] = (float)c;
                continue;
            }
            i -= MSPAN;
            if (i < CLEN + 1) {
                double c = 1.0;
                for (int k = 0; k < (int)i; k++) c *= 0.9;
                g_apow[i] = (float)c;
                continue;
            }
            i -= (CLEN + 1);
            if (i < 64) {   // zero the over-read tails (K=32 last-row safety)
                int arr = (int)(i >> 4), j = (int)(i & 15);
                __half zz = __float2half_rn(0.f);
                __half* p = (arr == 0) ? g_Fph : (arr == 1) ? g_Fpl
                           : (arr == 2) ? g_Rph : g_Rpl;
                p[MROWS * DD + j] = zz;
                continue;
            }
            i -= 64;
            out[i] = 0.f;
        }
    }
}

// ------- scan carries -------
__global__ void k_scan2() {
    const int d = threadIdx.x;
    const int b = blockIdx.x;
    const size_t base = (size_t)b * TPAD * DD;
    if (blockIdx.y == 0) {
        float carry = 0.f;
        const float a64 = g_apow[CLEN];
#pragma unroll 1
        for (int c = 0; c < NCHUNK; c++) {
            g_carryF[(b * NCHUNK + c) * DD + d] = carry;
            if (c < NCHUNK - 1) {
                float E = g_Ltmp[base + (size_t)((c + 1) * CLEN) * DD + d];
                carry = fmaf(a64, carry, E);
            }
        }
    } else {
        float carry = 0.f;
#pragma unroll 1
        for (int c = NCHUNK - 1; c >= 0; c--) {
            g_carryR[(b * NCHUNK + c) * DD + d] = carry;
            if (c > 0) {
                int len = min(CLEN, T_LEN - c * CLEN);
                float M = g_Mtmp[base + (size_t)(c * CLEN) * DD + d];
                carry = fmaf(g_apow[len], carry, M);
            }
        }
    }
}

// ------- apply carries + fp16 hi/lo split -------
constexpr int SC3_Q = DD / 4;
__global__ void __launch_bounds__(256) k_scan3() {
    int idx = blockIdx.x * 256 + threadIdx.x;
    const int total = 2 * BB * TPAD * SC3_Q;
    if (idx >= total) return;
    const int q = idx % SC3_Q;
    int rem = idx / SC3_Q;
    const int r = rem % TPAD;
    rem /= TPAD;
    const int b = rem % BB;
    const int dir = rem / BB;
    const int d = q * 4;
    const size_t ro = ((size_t)b * TPAD + r) * DD + d;

    float v[4];
    if (dir == 0) {
        __half zero = __float2half_rn(0.f);
        if (r == 0) {
            ((__half2*)&g_Fph[ro])[0] = __half2half2(zero);
            ((__half2*)&g_Fph[ro])[1] = __half2half2(zero);
            ((__half2*)&g_Fpl[ro])[0] = __half2half2(zero);
            ((__half2*)&g_Fpl[ro])[1] = __half2half2(zero);
            return;
        }
        int t = r - 1;
        int chunk = t >> 6;
        float p = g_apow[(t & 63) + 1];
        float4 L = *(const float4*)&g_Ltmp[ro];
        float4 C = *(const float4*)&g_carryF[(b * NCHUNK + chunk) * DD + d];
        v[0] = fmaf(p, C.x, L.x); v[1] = fmaf(p, C.y, L.y);
        v[2] = fmaf(p, C.z, L.z); v[3] = fmaf(p, C.w, L.w);
        __half2 h0 = __floats2half2_rn(v[0], v[1]);
        __half2 h1 = __floats2half2_rn(v[2], v[3]);
        float2 f0 = __half22float2(h0), f1 = __half22float2(h1);
        ((__half2*)&g_Fph[ro])[0] = h0;
        ((__half2*)&g_Fph[ro])[1] = h1;
        ((__half2*)&g_Fpl[ro])[0] = __floats2half2_rn(v[0] - f0.x, v[1] - f0.y);
        ((__half2*)&g_Fpl[ro])[1] = __floats2half2_rn(v[2] - f1.x, v[3] - f1.y);
    } else {
        __half zero = __float2half_rn(0.f);
        if (r == T_LEN) {
            ((__half2*)&g_Rph[ro])[0] = __half2half2(zero);
            ((__half2*)&g_Rph[ro])[1] = __half2half2(zero);
            ((__half2*)&g_Rpl[ro])[0] = __half2half2(zero);
            ((__half2*)&g_Rpl[ro])[1] = __half2half2(zero);
            return;
        }
        int t = r;
        int chunk = t >> 6;
        int end = min(T_LEN, (chunk + 1) << 6);
        float p = g_apow[end - t];
        float4 M = *(const float4*)&g_Mtmp[ro];
        float4 C = *(const float4*)&g_carryR[(b * NCHUNK + chunk) * DD + d];
        v[0] = fmaf(p, C.x, M.x); v[1] = fmaf(p, C.y, M.y);
        v[2] = fmaf(p, C.z, M.z); v[3] = fmaf(p, C.w, M.w);
        __half2 h0 = __floats2half2_rn(v[0], v[1]);
        __half2 h1 = __floats2half2_rn(v[2], v[3]);
        float2 f0 = __half22float2(h0), f1 = __half22float2(h1);
        ((__half2*)&g_Rph[ro])[0] = h0;
        ((__half2*)&g_Rph[ro])[1] = h1;
        ((__half2*)&g_Rpl[ro])[0] = __floats2half2_rn(v[0] - f0.x, v[1] - f0.y);
        ((__half2*)&g_Rpl[ro])[1] = __floats2half2_rn(v[2] - f1.x, v[3] - f1.y);
    }
}

// ---------- projections: uniform K=32 2-pass; z: 0->PX(Fp,W1a,+Pq) 1->PY(Fp,W1b)
// ---------- 2->PC(Rp,W1c, into g_PE); k_add then folds PE = PC + PY
constexpr int PJ_SB = 272;
constexpr uint32_t P2_AH = 0;        // 128*80 = 10240
constexpr uint32_t P2_AL = 10240;
constexpr uint32_t P2_B  = 20480;    // 32*272 = 8704
constexpr uint32_t PJ_STAGE = 29184;
constexpr uint32_t PJ_SMEM = 2 * PJ_STAGE;   // 58368

__global__ void __launch_bounds__(256) k_proj() {
    extern __shared__ char sm[];
    const uint32_t sb = smem_u32(sm);
    const int z = blockIdx.z;
    const int m0 = blockIdx.x * 128;
    const int n0 = blockIdx.y * 128;
    const int tid = threadIdx.x;
    const int lane = tid & 31;
    const int w = tid >> 5;
    const int mw = w & 3;
    const int nw = w >> 2;

    const __half* Ah = (z == 2) ? g_Rph : g_Fph;
    const __half* Al = (z == 2) ? g_Rpl : g_Fpl;
    __half* P = (z == 0) ? g_PX : (z == 1 ? g_PY : g_PE);

    const int amm = tid >> 1, aseg = tid & 1;
    const int am = (m0 + amm < MROWS) ? (m0 + amm) : 0;
    const int bkr = tid >> 4, bns = tid & 15;

    float acc[2][8][4];
#pragma unroll
    for (int i = 0; i < 2; i++)
#pragma unroll
        for (int j = 0; j < 8; j++)
#pragma unroll
            for (int c = 0; c < 4; c++) acc[i][j][c] = 0.f;

    const uint32_t bRel = (uint32_t)((lane & 15) * PJ_SB + (nw * 64 + (lane >> 4) * 8) * 2);
    const uint32_t aRel32 = (uint32_t)((mw * 32 + (lane & 15)) * 80 + (lane >> 4) * 16);

    auto stage32 = [&](int cc) {
        const uint32_t st = sb + (uint32_t)(cc & 1) * PJ_STAGE;
        const int k0 = cc * 32;
        const size_t asrc = (size_t)am * DD + k0 + aseg * 16;
        const uint32_t adst = (uint32_t)(amm * 80 + aseg * 32);
        cp16(st + P2_AH + adst,      Ah + asrc);
        cp16(st + P2_AH + adst + 16, Ah + asrc + 8);
        cp16(st + P2_AL + adst,      Al + asrc);
        cp16(st + P2_AL + adst + 16, Al + asrc + 8);
#pragma unroll
        for (int h = 0; h < 2; h++) {
            int kr = bkr + h * 16;
            const size_t bsrc = ((size_t)(z * KPAD + k0 + kr)) * H1 + n0 + bns * 8;
            cp16(st + P2_B + (uint32_t)(kr * PJ_SB + bns * 16), g_W1h3 + bsrc);
        }
        cp_commit();
    };
    stage32(0);
    cp_wait<0>();
    __syncthreads();
#pragma unroll 1
    for (int c = 0; c < 10; c++) {
        if (c < 9) stage32(c + 1);
        const uint32_t st = sb + (uint32_t)(c & 1) * PJ_STAGE;
#pragma unroll
        for (int s = 0; s < 2; s++) {
            uint32_t ah[2][4], al[2][4];
            ldsm_x4(ah[0], st + P2_AH + aRel32 + s * 32);
            ldsm_x4(ah[1], st + P2_AH + aRel32 + s * 32 + 16 * 80);
            ldsm_x4(al[0], st + P2_AL + aRel32 + s * 32);
            ldsm_x4(al[1], st + P2_AL + aRel32 + s * 32 + 16 * 80);
            const uint32_t kbq = st + P2_B + bRel + (uint32_t)(s * 16 * PJ_SB);
#pragma unroll
            for (int g = 0; g < 4; g++) {
                uint32_t bh[4];
                ldsm_x4_t(bh, kbq + g * 32);
#pragma unroll
                for (int m = 0; m < 2; m++) {
                    mma16816(acc[m][2 * g],     ah[m], bh);
                    mma16816(acc[m][2 * g + 1], ah[m], bh + 2);
                    mma16816(acc[m][2 * g],     al[m], bh);
                    mma16816(acc[m][2 * g + 1], al[m], bh + 2);
                }
            }
        }
        if (c < 9) { cp_wait<0>(); __syncthreads(); }
    }

#pragma unroll
    for (int m = 0; m < 2; m++) {
        int row0 = m0 + mw * 32 + m * 16 + (lane >> 2);
#pragma unroll
        for (int h = 0; h < 2; h++) {
            int row = row0 + h * 8;
            if (row >= MROWS) continue;
            const int col = n0 + nw * 64 + (lane & 3) * 2;
            __half2* pr = (__half2*)&P[(size_t)row * H1 + col];
            const float* qr = (z == 0) ? &g_Pq[(row / TPAD) * H1 + col] : nullptr;
#pragma unroll
            for (int nf = 0; nf < 8; nf++) {
                float vx = acc[m][nf][2 * h];
                float vy = acc[m][nf][2 * h + 1];
                if (z == 0) {
                    vx += qr[nf * 8];
                    vy += qr[nf * 8 + 1];
                }
                pr[nf * 4] = __floats2half2_rn(vx, vy);
            }
        }
    }
}

// ------- PE = PC + PY (elementwise fp16) -------
__global__ void __launch_bounds__(256) k_add() {
    size_t i = ((size_t)blockIdx.x * 256 + threadIdx.x) * 8;
    if (i >= (size_t)MROWS * H1) return;
    uint4 a = *(const uint4*)&g_PE[i];
    uint4 b = *(const uint4*)&g_PY[i];
    __half2* pa = (__half2*)&a;
    const __half2* pb = (const __half2*)&b;
#pragma unroll
    for (int j = 0; j < 4; j++) pa[j] = __hadd2(pa[j], pb[j]);
    *(uint4*)&g_PE[i] = a;
}

// ---- main: fp16 mma GEMM2, register-pipelined A-gen (R13 structure) ----
constexpr int SA_STRIDE = 144;
constexpr int SB_STRIDE = 528;
constexpr uint32_t OFF_AH   = 0;
constexpr uint32_t OFF_BH   = 9216;
constexpr uint32_t STAGE_SZ = 43008;
constexpr uint32_t OFF_HDR  = 86016;
constexpr uint32_t OFF_OS   = OFF_HDR;
constexpr uint32_t OFF_OE   = OFF_HDR + 256;
constexpr uint32_t OFF_CF   = OFF_HDR + 512;
constexpr uint32_t OFF_W3A  = OFF_HDR + 768;
constexpr uint32_t OFF_W3B  = OFF_HDR + 1792;
constexpr uint32_t OFF_SH2  = OFF_HDR + 2816;
constexpr uint32_t OFF_RED  = OFF_HDR + 3840;
constexpr uint32_t SMEM_MAIN = OFF_HDR + 5888;

__global__ void __launch_bounds__(256, 2) k_main(const float* __restrict__ W3,
                                                 float* __restrict__ out) {
    extern __shared__ char sm[];
    const uint32_t sb = smem_u32(sm);
    const int tid = threadIdx.x;
    const int lane = tid & 31;
    const int w = tid >> 5;
    const int mw = w & 1;
    const int nw = w >> 1;
    const int batch = blockIdx.y;
    const int c0i = blockIdx.x * 64;
    const int n0 = blockIdx.z * 256;

    int*   sOS = (int*)(sm + OFF_OS);
    int*   sOE = (int*)(sm + OFF_OE);
    float* sCF = (float*)(sm + OFF_CF);
    float* sW3a = (float*)(sm + OFF_W3A);
    float* sW3b = (float*)(sm + OFF_W3B);
    float* sSh2 = (float*)(sm + OFF_SH2);
    float* sRed = (float*)(sm + OFF_RED);

    if (tid < 64) {
        int ci = c0i + tid;
        int offS = 0, offE = 0;
        float cf = 0.f;
        if (ci < NCAND) {
            int s = g_sidx[ci], e = g_eidx[ci];
            offS = (batch * TPAD + s) * H1;
            offE = (batch * TPAD + e + 1) * H1;
            cf = g_coef[e - s];
        }
        sOS[tid] = offS; sOE[tid] = offE; sCF[tid] = cf;
    }
    sW3a[tid] = W3[n0 + tid];
    sW3b[tid] = W3[H2 + n0 + tid];
    sSh2[tid] = g_sh2[n0 + tid];
    __syncthreads();

    const int wrow = w * 8;
    const int myOS = sOS[wrow + (lane & 7)];
    const int myOE = sOE[wrow + (lane & 7)];
    const float myCF = sCF[wrow + (lane & 7)];
    const bool uni = (__shfl_sync(0xffffffffu, myOS, 0) ==
                      __shfl_sync(0xffffffffu, myOS, 7));
    const int offSu = __shfl_sync(0xffffffffu, myOS, 0);
    int offEr[8];
    float cfr[8];
#pragma unroll
    for (int rr = 0; rr < 8; rr++) {
        offEr[rr] = __shfl_sync(0xffffffffu, myOE, rr);
        cfr[rr] = __shfl_sync(0xffffffffu, myCF, rr);
    }
    int offSr[8];
#pragma unroll
    for (int rr = 0; rr < 8; rr++) offSr[rr] = __shfl_sync(0xffffffffu, myOS, rr);

    const int bkr = tid >> 5;
    const int bnc = tid & 31;

    const uint32_t aRel = OFF_AH + (uint32_t)((mw * 32 + (lane & 15)) * SA_STRIDE +
                                              ((lane >> 4) * 8) * 2);
    const uint32_t bRel = OFF_BH + (uint32_t)((lane & 15) * SB_STRIDE +
                                              (nw * 64 + (lane >> 4) * 8) * 2);

    float acc[2][8][4];
#pragma unroll
    for (int t = 0; t < 2; t++)
#pragma unroll
        for (int nf = 0; nf < 8; nf++)
#pragma unroll
            for (int c = 0; c < 4; c++) acc[t][nf][c] = 0.f;

    auto issueB = [&](int cc) {
        const uint32_t st = sb + (uint32_t)(cc & 1) * STAGE_SZ;
        const __half* bsrc = &g_W2h16[(size_t)(cc * 64) * H2 + n0];
#pragma unroll
        for (int it = 0; it < 8; it++) {
            int kr = bkr + it * 8;
            cp16(st + OFF_BH + (uint32_t)(kr * SB_STRIDE + bnc * 16),
                 bsrc + (size_t)kr * H2 + bnc * 8);
        }
        cp_commit();
    };

    __half2 er[8], xr[8], yr[8];
    auto ldA = [&](int cc) {
        const int kc = cc * 64 + 2 * lane;
#pragma unroll
        for (int rr = 0; rr < 8; rr++)
            er[rr] = *(const __half2*)&g_PE[offEr[rr] + kc];
        if (uni) {
            xr[0] = *(const __half2*)&g_PX[offSu + kc];
            yr[0] = *(const __half2*)&g_PY[offSu + kc];
        } else {
#pragma unroll
            for (int rr = 0; rr < 8; rr++) {
                xr[rr] = *(const __half2*)&g_PX[offSr[rr] + kc];
                yr[rr] = *(const __half2*)&g_PY[offSr[rr] + kc];
            }
        }
    };
    auto cvtStore = [&](int cc) {
        const uint32_t stoff = (uint32_t)(cc & 1) * STAGE_SZ;
        if (uni) {
            float2 x = __half22float2(xr[0]);
            float2 y = __half22float2(yr[0]);
#pragma unroll
            for (int rr = 0; rr < 8; rr++) {
                float2 e = __half22float2(er[rr]);
                float v0 = fmaxf(x.x + e.x - cfr[rr] * y.x, 0.f);
                float v1 = fmaxf(x.y + e.y - cfr[rr] * y.y, 0.f);
                __half2 h = __floats2half2_rn(v0, v1);
                uint32_t ad = stoff + (uint32_t)((wrow + rr) * SA_STRIDE + lane * 4);
                *(uint32_t*)(sm + OFF_AH + ad) = h2u(h);
            }
        } else {
#pragma unroll
            for (int rr = 0; rr < 8; rr++) {
                float2 x = __half22float2(xr[rr]);
                float2 y = __half22float2(yr[rr]);
                float2 e = __half22float2(er[rr]);
                float v0 = fmaxf(x.x + e.x - cfr[rr] * y.x, 0.f);
                float v1 = fmaxf(x.y + e.y - cfr[rr] * y.y, 0.f);
                __half2 h = __floats2half2_rn(v0, v1);
                uint32_t ad = stoff + (uint32_t)((wrow + rr) * SA_STRIDE + lane * 4);
                *(uint32_t*)(sm + OFF_AH + ad) = h2u(h);
            }
        }
    };

    issueB(0);
    ldA(0);
    cvtStore(0);
    cp_wait<0>();
    __syncthreads();

#pragma unroll 1
    for (int c = 0; c < 16; c++) {
        if (c < 15) {
            issueB(c + 1);
            ldA(c + 1);
        }
        const uint32_t st = sb + (uint32_t)(c & 1) * STAGE_SZ;
#pragma unroll
        for (int s = 0; s < 4; s++) {
            const uint32_t ka = st + aRel + (uint32_t)(s * 32);
            uint32_t ah[2][4];
            ldsm_x4(ah[0], ka);
            ldsm_x4(ah[1], ka + 16 * SA_STRIDE);
            const uint32_t kbq = st + bRel + (uint32_t)(s * 16 * SB_STRIDE);
#pragma unroll
            for (int p = 0; p < 4; p++) {
                uint32_t bq[4];
                ldsm_x4_t(bq, kbq + p * 32);
                mma16816(acc[0][2 * p],     ah[0], bq);
                mma16816(acc[1][2 * p],     ah[1], bq);
                mma16816(acc[0][2 * p + 1], ah[0], bq + 2);
                mma16816(acc[1][2 * p + 1], ah[1], bq + 2);
            }
        }
        if (c < 15) {
            cvtStore(c + 1);
            cp_wait<0>();
            __syncthreads();
        }
    }

    // ---- epilogue: relu(D + sh2) dot W3, reduce, atomicAdd ----
    float sums[4][2];
#pragma unroll
    for (int q = 0; q < 4; q++) { sums[q][0] = 0.f; sums[q][1] = 0.f; }
#pragma unroll
    for (int t = 0; t < 2; t++) {
#pragma unroll
        for (int nf = 0; nf < 8; nf++) {
            int n = nw * 64 + nf * 8 + (lane & 3) * 2;
            float sh0 = sSh2[n], sh1 = sSh2[n + 1];
            float wa0 = sW3a[n], wa1 = sW3a[n + 1];
            float wb0 = sW3b[n], wb1 = sW3b[n + 1];
            float v0 = fmaxf(acc[t][nf][0] + sh0, 0.f);
            float v1 = fmaxf(acc[t][nf][1] + sh1, 0.f);
            float v2 = fmaxf(acc[t][nf][2] + sh0, 0.f);
            float v3 = fmaxf(acc[t][nf][3] + sh1, 0.f);
            sums[t * 2][0]     = fmaf(v0, wa0, fmaf(v1, wa1, sums[t * 2][0]));
            sums[t * 2][1]     = fmaf(v0, wb0, fmaf(v1, wb1, sums[t * 2][1]));
            sums[t * 2 + 1][0] = fmaf(v2, wa0, fmaf(v3, wa1, sums[t * 2 + 1][0]));
            sums[t * 2 + 1][1] = fmaf(v2, wb0, fmaf(v3, wb1, sums[t * 2 + 1][1]));
        }
    }
#pragma unroll
    for (int q = 0; q < 4; q++) {
#pragma unroll
        for (int o = 0; o < 2; o++) {
            sums[q][o] += __shfl_xor_sync(0xffffffffu, sums[q][o], 1);
            sums[q][o] += __shfl_xor_sync(0xffffffffu, sums[q][o], 2);
        }
    }
    __syncthreads();
    if ((lane & 3) == 0) {
#pragma unroll
        for (int q = 0; q < 4; q++) {
            int rloc = mw * 32 + (q >> 1) * 16 + (q & 1) * 8 + (lane >> 2);
            sRed[nw * 128 + rloc * 2 + 0] = sums[q][0];
            sRed[nw * 128 + rloc * 2 + 1] = sums[q][1];
        }
    }
    __syncthreads();
    if (tid < 128) {
        int rloc = tid >> 1, o = tid & 1;
        int ci = c0i + rloc;
        if (ci < NCAND) {
            float v = sRed[rloc * 2 + o] + sRed[128 + rloc * 2 + o] +
                      sRed[256 + rloc * 2 + o] + sRed[384 + rloc * 2 + o];
            atomicAdd(&out[(size_t)(batch * NCAND + ci) * 2 + o], v);
        }
    }
}

// ---------------- launch ----------------
extern "C" void kernel_launch(void* const* d_in, const int* in_sizes, int n_in,
                              void* d_out, int out_size) {
    (void)in_sizes; (void)n_in; (void)out_size;
    const float* doc = (const float*)d_in[0];
    const float* qe  = (const float*)d_in[1];
    const float* W1  = (const float*)d_in[2];
    const float* g1  = (const float*)d_in[3];
    const float* b1  = (const float*)d_in[4];
    const float* m1  = (const float*)d_in[5];
    const float* v1  = (const float*)d_in[6];
    const float* W2  = (const float*)d_in[7];
    const float* g2  = (const float*)d_in[8];
    const float* b2  = (const float*)d_in[9];
    const float* m2  = (const float*)d_in[10];
    const float* v2  = (const float*)d_in[11];
    const float* W3  = (const float*)d_in[12];
    float* out = (float*)d_out;

    cudaFuncSetAttribute(k_main, cudaFuncAttributeMaxDynamicSharedMemorySize, SMEM_MAIN);
    cudaFuncSetAttribute(k_proj, cudaFuncAttributeMaxDynamicSharedMemorySize, PJ_SMEM);

    k_prep<<<PREP_GRID, 256>>>(doc, qe, W1, g1, b1, m1, v1, W2, g2, b2, m2, v2, out);
    k_scan2<<<dim3(BB, 2), DD>>>();
    k_scan3<<<(2 * BB * TPAD * SC3_Q + 255) / 256, 256>>>();
    k_proj<<<dim3((MROWS + 127) / 128, H1 / 128, 3), 256, PJ_SMEM>>>();
    k_add<<<(MROWS * H1 / 8 + 255) / 256, 256>>>();
    k_main<<<dim3((NCAND + 63) / 64, BB, 2), 256, SMEM_MAIN>>>(W3, out);
}